// round 1
// baseline (speedup 1.0000x reference)
#include <cuda_runtime.h>
#include <math.h>
#include <math_constants.h>

#define DIM     1024
#define NHEADS  16
#define HDIM    64
#define HIDDEN  4096
#define BATCH   2
#define SEQ     2048
#define NTOK    (BATCH * SEQ)
#define EPS     1e-5f

// ---------------- scratch (static device globals; no allocs) ----------------
__device__ float g_h   [NTOK * DIM];     // rmsnorm1 output
__device__ float g_q   [NTOK * DIM];
__device__ float g_k   [NTOK * DIM];
__device__ float g_v   [NTOK * DIM];
__device__ float g_att [NTOK * DIM];     // attention output (B,S,H,D) flattened
__device__ float g_x2  [NTOK * DIM];     // residual after attention
__device__ float g_h2  [NTOK * DIM];     // rmsnorm2 output
__device__ float g_gate[NTOK * HIDDEN];  // gate, then silu(gate)*up in-place
__device__ float g_up  [NTOK * HIDDEN];

// ---------------- RMSNorm: one block per token ----------------
__global__ void rmsnorm_kernel(const float* __restrict__ x,
                               const float* __restrict__ w,
                               float* __restrict__ out) {
    int t = blockIdx.x;
    int tid = threadIdx.x;                      // 256 threads
    const float4* xr = reinterpret_cast<const float4*>(x + (size_t)t * DIM);
    float4 v = xr[tid];                         // 1024/4 = 256 float4
    float ss = v.x * v.x + v.y * v.y + v.z * v.z + v.w * v.w;
    #pragma unroll
    for (int o = 16; o > 0; o >>= 1) ss += __shfl_xor_sync(0xFFFFFFFFu, ss, o);
    __shared__ float red[8];
    if ((tid & 31) == 0) red[tid >> 5] = ss;
    __syncthreads();
    if (tid < 8) {
        float s = red[tid];
        #pragma unroll
        for (int o = 4; o > 0; o >>= 1) s += __shfl_xor_sync(0xFFu, s, o);
        if (tid == 0) red[0] = s;
    }
    __syncthreads();
    float scale = rsqrtf(red[0] * (1.0f / DIM) + EPS);
    float4 wv = reinterpret_cast<const float4*>(w)[tid];
    float4 o4;
    o4.x = v.x * scale * wv.x;
    o4.y = v.y * scale * wv.y;
    o4.z = v.z * scale * wv.z;
    o4.w = v.w * scale * wv.w;
    reinterpret_cast<float4*>(out + (size_t)t * DIM)[tid] = o4;
}

// ---------------- SGEMM (NT): C[m,n] = sum_k A[m,k]*B[n,k] (+ res) ----------
// A: [M,K] row-major, B: [N,K] row-major. 128x128 tile, BK=8, 256 threads,
// 8x8 per-thread microtile. M,N multiples of 128; K multiple of 8.
__global__ __launch_bounds__(256)
void sgemm_nt(const float* __restrict__ A, const float* __restrict__ B,
              const float* __restrict__ res, float* __restrict__ C,
              int M, int N, int K) {
    constexpr int BM = 128, BN = 128, BK = 8;
    __shared__ float As[BK][BM];
    __shared__ float Bs[BK][BN];

    int tid = threadIdx.x;
    int tx = tid & 15;        // 16 cols of threads (N dim)
    int ty = tid >> 4;        // 16 rows of threads (M dim)
    int m0 = blockIdx.y * BM;
    int n0 = blockIdx.x * BN;

    float acc[8][8];
    #pragma unroll
    for (int i = 0; i < 8; i++)
        #pragma unroll
        for (int j = 0; j < 8; j++) acc[i][j] = 0.0f;

    int lrow = tid >> 1;              // 0..127
    int lcol = (tid & 1) << 2;        // 0 or 4
    const float* Ag = A + (size_t)(m0 + lrow) * K + lcol;
    const float* Bg = B + (size_t)(n0 + lrow) * K + lcol;

    for (int k0 = 0; k0 < K; k0 += BK) {
        float4 a4 = *reinterpret_cast<const float4*>(Ag + k0);
        float4 b4 = *reinterpret_cast<const float4*>(Bg + k0);
        As[lcol + 0][lrow] = a4.x; As[lcol + 1][lrow] = a4.y;
        As[lcol + 2][lrow] = a4.z; As[lcol + 3][lrow] = a4.w;
        Bs[lcol + 0][lrow] = b4.x; Bs[lcol + 1][lrow] = b4.y;
        Bs[lcol + 2][lrow] = b4.z; Bs[lcol + 3][lrow] = b4.w;
        __syncthreads();
        #pragma unroll
        for (int k = 0; k < BK; k++) {
            float a[8], b[8];
            *reinterpret_cast<float4*>(a)     = *reinterpret_cast<float4*>(&As[k][ty * 8]);
            *reinterpret_cast<float4*>(a + 4) = *reinterpret_cast<float4*>(&As[k][ty * 8 + 4]);
            *reinterpret_cast<float4*>(b)     = *reinterpret_cast<float4*>(&Bs[k][tx * 8]);
            *reinterpret_cast<float4*>(b + 4) = *reinterpret_cast<float4*>(&Bs[k][tx * 8 + 4]);
            #pragma unroll
            for (int i = 0; i < 8; i++)
                #pragma unroll
                for (int j = 0; j < 8; j++) acc[i][j] = fmaf(a[i], b[j], acc[i][j]);
        }
        __syncthreads();
    }

    #pragma unroll
    for (int i = 0; i < 8; i++) {
        size_t row = (size_t)(m0 + ty * 8 + i);
        size_t base = row * N + n0 + tx * 8;
        if (res) {
            #pragma unroll
            for (int j = 0; j < 8; j++) C[base + j] = acc[i][j] + res[base + j];
        } else {
            #pragma unroll
            for (int j = 0; j < 8; j++) C[base + j] = acc[i][j];
        }
    }
}

// ---------------- Causal flash attention (fp32) ----------------
// Q,K,V layout: [B, S, H*D] with head h at column offset h*HDIM.
// Grid: (S/64, NHEADS, BATCH); 256 threads; 64x64 tiles; D=64.
__global__ __launch_bounds__(256)
void attn_kernel(const float* __restrict__ Q, const float* __restrict__ K,
                 const float* __restrict__ V, float* __restrict__ O) {
    constexpr int BM = 64, BN = 64;
    __shared__ float Qst[HDIM][BM];       // Q transposed [d][m], scale folded in
    __shared__ float KP [HDIM * BN];      // K transposed [d][n], reused as P[m][n]
    __shared__ float Vs [BN][HDIM];       // V [n][d]

    int qb = blockIdx.x, h = blockIdx.y, b = blockIdx.z;
    int tid = threadIdx.x;
    int tx = tid & 15;     // n / d-out dimension (cols)
    int ty = tid >> 4;     // m dimension (rows)
    const float scale = 0.125f;  // 1/sqrt(64)
    size_t base = (size_t)b * SEQ * DIM + (size_t)h * HDIM;

    // load Q tile transposed, fold scale
    #pragma unroll
    for (int p = 0; p < 4; p++) {
        int r = p * 16 + (tid >> 4);
        int c = (tid & 15) << 2;
        float4 q4 = *reinterpret_cast<const float4*>(Q + base + (size_t)(qb * 64 + r) * DIM + c);
        Qst[c + 0][r] = q4.x * scale; Qst[c + 1][r] = q4.y * scale;
        Qst[c + 2][r] = q4.z * scale; Qst[c + 3][r] = q4.w * scale;
    }

    float o_acc[4][4];
    float m_i[4], l_i[4];
    #pragma unroll
    for (int i = 0; i < 4; i++) {
        m_i[i] = -CUDART_INF_F; l_i[i] = 0.0f;
        #pragma unroll
        for (int j = 0; j < 4; j++) o_acc[i][j] = 0.0f;
    }

    for (int kb = 0; kb <= qb; kb++) {
        __syncthreads();  // previous-iter reads of KP/Vs done (and Q load on iter 0)
        // load K tile transposed + V tile direct
        #pragma unroll
        for (int p = 0; p < 4; p++) {
            int r = p * 16 + (tid >> 4);
            int c = (tid & 15) << 2;
            const float* kg = K + base + (size_t)(kb * 64 + r) * DIM + c;
            const float* vg = V + base + (size_t)(kb * 64 + r) * DIM + c;
            float4 k4 = *reinterpret_cast<const float4*>(kg);
            float4 v4 = *reinterpret_cast<const float4*>(vg);
            KP[(c + 0) * BM + r] = k4.x; KP[(c + 1) * BM + r] = k4.y;
            KP[(c + 2) * BM + r] = k4.z; KP[(c + 3) * BM + r] = k4.w;
            *reinterpret_cast<float4*>(&Vs[r][c]) = v4;
        }
        __syncthreads();

        // S = (scaled Q) K^T : 4x4 per thread
        float s[4][4];
        #pragma unroll
        for (int i = 0; i < 4; i++)
            #pragma unroll
            for (int j = 0; j < 4; j++) s[i][j] = 0.0f;
        #pragma unroll 8
        for (int d = 0; d < HDIM; d++) {
            float a[4], bb[4];
            *reinterpret_cast<float4*>(a)  = *reinterpret_cast<float4*>(&Qst[d][ty * 4]);
            *reinterpret_cast<float4*>(bb) = *reinterpret_cast<float4*>(&KP[d * BM + tx * 4]);
            #pragma unroll
            for (int i = 0; i < 4; i++)
                #pragma unroll
                for (int j = 0; j < 4; j++) s[i][j] = fmaf(a[i], bb[j], s[i][j]);
        }

        if (kb == qb) {  // causal mask on diagonal tile
            #pragma unroll
            for (int i = 0; i < 4; i++)
                #pragma unroll
                for (int j = 0; j < 4; j++)
                    if (tx * 4 + j > ty * 4 + i) s[i][j] = -CUDART_INF_F;
        }

        // online softmax: row reductions across the 16 tx lanes (same warp)
        float alpha[4];
        #pragma unroll
        for (int i = 0; i < 4; i++) {
            float rm = fmaxf(fmaxf(s[i][0], s[i][1]), fmaxf(s[i][2], s[i][3]));
            #pragma unroll
            for (int o = 8; o > 0; o >>= 1) rm = fmaxf(rm, __shfl_xor_sync(0xFFFFFFFFu, rm, o));
            float mn = fmaxf(m_i[i], rm);
            alpha[i] = __expf(m_i[i] - mn);   // 0 if m_i was -inf
            m_i[i] = mn;
            float rs = 0.0f;
            #pragma unroll
            for (int j = 0; j < 4; j++) {
                s[i][j] = __expf(s[i][j] - mn);   // -inf -> 0
                rs += s[i][j];
            }
            #pragma unroll
            for (int o = 8; o > 0; o >>= 1) rs += __shfl_xor_sync(0xFFFFFFFFu, rs, o);
            l_i[i] = l_i[i] * alpha[i] + rs;
        }

        __syncthreads();  // all threads finished reading KP as K
        // write P into KP buffer as [m][n]
        #pragma unroll
        for (int i = 0; i < 4; i++)
            #pragma unroll
            for (int j = 0; j < 4; j++)
                KP[(ty * 4 + i) * BN + tx * 4 + j] = s[i][j];
        __syncthreads();

        // O = O*alpha + P V
        #pragma unroll
        for (int i = 0; i < 4; i++)
            #pragma unroll
            for (int j = 0; j < 4; j++) o_acc[i][j] *= alpha[i];
        #pragma unroll 8
        for (int n = 0; n < BN; n++) {
            float p[4], vv[4];
            #pragma unroll
            for (int i = 0; i < 4; i++) p[i] = KP[(ty * 4 + i) * BN + n];
            *reinterpret_cast<float4*>(vv) = *reinterpret_cast<float4*>(&Vs[n][tx * 4]);
            #pragma unroll
            for (int i = 0; i < 4; i++)
                #pragma unroll
                for (int j = 0; j < 4; j++) o_acc[i][j] = fmaf(p[i], vv[j], o_acc[i][j]);
        }
    }

    // normalize and write
    #pragma unroll
    for (int i = 0; i < 4; i++) {
        float inv = 1.0f / l_i[i];
        size_t row = (size_t)(qb * 64 + ty * 4 + i);
        float* og = O + base + row * DIM + tx * 4;
        #pragma unroll
        for (int j = 0; j < 4; j++) og[j] = o_acc[i][j] * inv;
    }
}

// ---------------- SiLU(gate) * up, in-place into gate ----------------
__global__ void silu_mul_kernel(float* __restrict__ gate, const float* __restrict__ up, int n4) {
    int i = blockIdx.x * blockDim.x + threadIdx.x;
    if (i >= n4) return;
    float4 g = reinterpret_cast<float4*>(gate)[i];
    float4 u = reinterpret_cast<const float4*>(up)[i];
    float4 r;
    r.x = g.x / (1.0f + expf(-g.x)) * u.x;
    r.y = g.y / (1.0f + expf(-g.y)) * u.y;
    r.z = g.z / (1.0f + expf(-g.z)) * u.z;
    r.w = g.w / (1.0f + expf(-g.w)) * u.w;
    reinterpret_cast<float4*>(gate)[i] = r;
}

// ---------------- launch ----------------
extern "C" void kernel_launch(void* const* d_in, const int* in_sizes, int n_in,
                              void* d_out, int out_size) {
    const float* x     = (const float*)d_in[0];
    const float* wq    = (const float*)d_in[1];
    const float* wk    = (const float*)d_in[2];
    const float* wv    = (const float*)d_in[3];
    const float* wo    = (const float*)d_in[4];
    const float* wgate = (const float*)d_in[5];
    const float* wup   = (const float*)d_in[6];
    const float* wdown = (const float*)d_in[7];
    const float* n1w   = (const float*)d_in[8];
    const float* n2w   = (const float*)d_in[9];
    float* out = (float*)d_out;

    float *h, *q, *k, *v, *att, *x2, *h2, *gate, *up;
    cudaGetSymbolAddress((void**)&h,    g_h);
    cudaGetSymbolAddress((void**)&q,    g_q);
    cudaGetSymbolAddress((void**)&k,    g_k);
    cudaGetSymbolAddress((void**)&v,    g_v);
    cudaGetSymbolAddress((void**)&att,  g_att);
    cudaGetSymbolAddress((void**)&x2,   g_x2);
    cudaGetSymbolAddress((void**)&h2,   g_h2);
    cudaGetSymbolAddress((void**)&gate, g_gate);
    cudaGetSymbolAddress((void**)&up,   g_up);

    // 1. h = rmsnorm(x, norm1_w)
    rmsnorm_kernel<<<NTOK, 256>>>(x, n1w, h);

    // 2. q/k/v = h @ W^T
    dim3 g1(DIM / 128, NTOK / 128);
    sgemm_nt<<<g1, 256>>>(h, wq, nullptr, q, NTOK, DIM, DIM);
    sgemm_nt<<<g1, 256>>>(h, wk, nullptr, k, NTOK, DIM, DIM);
    sgemm_nt<<<g1, 256>>>(h, wv, nullptr, v, NTOK, DIM, DIM);

    // 3. causal flash attention
    dim3 ga(SEQ / 64, NHEADS, BATCH);
    attn_kernel<<<ga, 256>>>(q, k, v, att);

    // 4. x2 = x + att @ wo^T
    sgemm_nt<<<g1, 256>>>(att, wo, x, x2, NTOK, DIM, DIM);

    // 5. h2 = rmsnorm(x2, norm2_w)
    rmsnorm_kernel<<<NTOK, 256>>>(x2, n2w, h2);

    // 6. gate/up GEMMs
    dim3 g2(HIDDEN / 128, NTOK / 128);
    sgemm_nt<<<g2, 256>>>(h2, wgate, nullptr, gate, NTOK, HIDDEN, DIM);
    sgemm_nt<<<g2, 256>>>(h2, wup,   nullptr, up,   NTOK, HIDDEN, DIM);

    // 7. gate = silu(gate) * up
    int n4 = NTOK * HIDDEN / 4;
    silu_mul_kernel<<<(n4 + 255) / 256, 256>>>(gate, up, n4);

    // 8. out = x2 + act @ wdown^T
    sgemm_nt<<<g1, 256>>>(gate, wdown, x2, out, NTOK, DIM, HIDDEN);
}

// round 2
// speedup vs baseline: 2.1396x; 2.1396x over previous
#include <cuda_runtime.h>
#include <math.h>
#include <math_constants.h>

#define DIM     1024
#define NHEADS  16
#define HDIM    64
#define HIDDEN  4096
#define BATCH   2
#define SEQ     2048
#define NTOK    (BATCH * SEQ)
#define EPS     1e-5f

// ---------------- scratch (static device globals; no allocs) ----------------
__device__ float g_h   [NTOK * DIM];
__device__ float g_q   [NTOK * DIM];
__device__ float g_k   [NTOK * DIM];
__device__ float g_v   [NTOK * DIM];
__device__ float g_att [NTOK * DIM];
__device__ float g_x2  [NTOK * DIM];
__device__ float g_h2  [NTOK * DIM];
__device__ float g_gate[NTOK * HIDDEN];
__device__ float g_up  [NTOK * HIDDEN];

// ---------------- RMSNorm: one block per token ----------------
__global__ void rmsnorm_kernel(const float* __restrict__ x,
                               const float* __restrict__ w,
                               float* __restrict__ out) {
    int t = blockIdx.x;
    int tid = threadIdx.x;                      // 256 threads
    const float4* xr = reinterpret_cast<const float4*>(x + (size_t)t * DIM);
    float4 v = xr[tid];
    float ss = v.x * v.x + v.y * v.y + v.z * v.z + v.w * v.w;
    #pragma unroll
    for (int o = 16; o > 0; o >>= 1) ss += __shfl_xor_sync(0xFFFFFFFFu, ss, o);
    __shared__ float red[8];
    if ((tid & 31) == 0) red[tid >> 5] = ss;
    __syncthreads();
    if (tid < 8) {
        float s = red[tid];
        #pragma unroll
        for (int o = 4; o > 0; o >>= 1) s += __shfl_xor_sync(0xFFu, s, o);
        if (tid == 0) red[0] = s;
    }
    __syncthreads();
    float scale = rsqrtf(red[0] * (1.0f / DIM) + EPS);
    float4 wv = reinterpret_cast<const float4*>(w)[tid];
    float4 o4;
    o4.x = v.x * scale * wv.x;
    o4.y = v.y * scale * wv.y;
    o4.z = v.z * scale * wv.z;
    o4.w = v.w * scale * wv.w;
    reinterpret_cast<float4*>(out + (size_t)t * DIM)[tid] = o4;
}

// ---------------- tf32 tensor-core GEMM (NT): C = A B^T (+ res) -------------
// A: [M,K] row-major, B: [N,K] row-major. 128x128 block tile, BK=16,
// 8 warps (2x4), warp tile 64x32, mma.sync.m16n8k8.tf32.
__device__ __forceinline__ unsigned f2tf(float f) {
    unsigned r; asm("cvt.rna.tf32.f32 %0, %1;" : "=r"(r) : "f"(f)); return r;
}

__global__ __launch_bounds__(256)
void gemm_tf32(const float* __restrict__ A, const float* __restrict__ B,
               const float* __restrict__ res, float* __restrict__ C,
               int M, int N, int K) {
    constexpr int BM = 128, BN = 128, BK = 16, LDA = 20;  // stride 20: conflict-free frags
    __shared__ unsigned As[BM * LDA];
    __shared__ unsigned Bs[BN * LDA];

    int tid  = threadIdx.x;
    int lane = tid & 31;
    int wid  = tid >> 5;
    int wm = (wid & 1) * 64;     // warp m offset (2 warps in m)
    int wn = (wid >> 1) * 32;    // warp n offset (4 warps in n)
    int m0 = blockIdx.y * BM;
    int n0 = blockIdx.x * BN;

    float acc[4][4][4];
    #pragma unroll
    for (int i = 0; i < 4; i++)
        #pragma unroll
        for (int j = 0; j < 4; j++)
            #pragma unroll
            for (int c = 0; c < 4; c++) acc[i][j][c] = 0.0f;

    int lr = tid >> 2;            // 0..63
    int lc = (tid & 3) << 2;      // 0,4,8,12
    const float* Ag = A + (size_t)(m0 + lr) * K + lc;
    const float* Bg = B + (size_t)(n0 + lr) * K + lc;
    size_t rowstep = (size_t)64 * K;

    float4 apf[2], bpf[2];
    apf[0] = *reinterpret_cast<const float4*>(Ag);
    apf[1] = *reinterpret_cast<const float4*>(Ag + rowstep);
    bpf[0] = *reinterpret_cast<const float4*>(Bg);
    bpf[1] = *reinterpret_cast<const float4*>(Bg + rowstep);

    for (int k0 = 0; k0 < K; k0 += BK) {
        #pragma unroll
        for (int p = 0; p < 2; p++) {
            unsigned* as = &As[(lr + p * 64) * LDA + lc];
            float4 a = apf[p];
            as[0] = f2tf(a.x); as[1] = f2tf(a.y); as[2] = f2tf(a.z); as[3] = f2tf(a.w);
            unsigned* bs = &Bs[(lr + p * 64) * LDA + lc];
            float4 b = bpf[p];
            bs[0] = f2tf(b.x); bs[1] = f2tf(b.y); bs[2] = f2tf(b.z); bs[3] = f2tf(b.w);
        }
        __syncthreads();

        if (k0 + BK < K) {
            apf[0] = *reinterpret_cast<const float4*>(Ag + k0 + BK);
            apf[1] = *reinterpret_cast<const float4*>(Ag + rowstep + k0 + BK);
            bpf[0] = *reinterpret_cast<const float4*>(Bg + k0 + BK);
            bpf[1] = *reinterpret_cast<const float4*>(Bg + rowstep + k0 + BK);
        }

        #pragma unroll
        for (int ks = 0; ks < 2; ks++) {
            int kk = ks * 8;
            unsigned af[4][4], bf[4][2];
            #pragma unroll
            for (int mi = 0; mi < 4; mi++) {
                int m = wm + mi * 16 + (lane >> 2);
                af[mi][0] = As[m * LDA + kk + (lane & 3)];
                af[mi][1] = As[(m + 8) * LDA + kk + (lane & 3)];
                af[mi][2] = As[m * LDA + kk + 4 + (lane & 3)];
                af[mi][3] = As[(m + 8) * LDA + kk + 4 + (lane & 3)];
            }
            #pragma unroll
            for (int ni = 0; ni < 4; ni++) {
                int n = wn + ni * 8 + (lane >> 2);
                bf[ni][0] = Bs[n * LDA + kk + (lane & 3)];
                bf[ni][1] = Bs[n * LDA + kk + 4 + (lane & 3)];
            }
            #pragma unroll
            for (int mi = 0; mi < 4; mi++)
                #pragma unroll
                for (int ni = 0; ni < 4; ni++)
                    asm volatile(
                        "mma.sync.aligned.m16n8k8.row.col.f32.tf32.tf32.f32 "
                        "{%0,%1,%2,%3}, {%4,%5,%6,%7}, {%8,%9}, {%0,%1,%2,%3};"
                        : "+f"(acc[mi][ni][0]), "+f"(acc[mi][ni][1]),
                          "+f"(acc[mi][ni][2]), "+f"(acc[mi][ni][3])
                        : "r"(af[mi][0]), "r"(af[mi][1]), "r"(af[mi][2]), "r"(af[mi][3]),
                          "r"(bf[ni][0]), "r"(bf[ni][1]));
        }
        __syncthreads();
    }

    // epilogue: c0/c1 at (row, 2c), (row, 2c+1); c2/c3 at row+8
    int gr = lane >> 2;
    int gc = (lane & 3) * 2;
    #pragma unroll
    for (int mi = 0; mi < 4; mi++) {
        #pragma unroll
        for (int ni = 0; ni < 4; ni++) {
            size_t row = (size_t)(m0 + wm + mi * 16 + gr);
            size_t col = (size_t)(n0 + wn + ni * 8 + gc);
            float2 v0 = make_float2(acc[mi][ni][0], acc[mi][ni][1]);
            float2 v1 = make_float2(acc[mi][ni][2], acc[mi][ni][3]);
            if (res) {
                float2 r0 = *reinterpret_cast<const float2*>(res + row * N + col);
                float2 r1 = *reinterpret_cast<const float2*>(res + (row + 8) * N + col);
                v0.x += r0.x; v0.y += r0.y; v1.x += r1.x; v1.y += r1.y;
            }
            *reinterpret_cast<float2*>(C + row * N + col) = v0;
            *reinterpret_cast<float2*>(C + (row + 8) * N + col) = v1;
        }
    }
}

// ---------------- Causal flash attention (fp32) ----------------
__global__ __launch_bounds__(256)
void attn_kernel(const float* __restrict__ Q, const float* __restrict__ K,
                 const float* __restrict__ V, float* __restrict__ O) {
    constexpr int BM = 64, BN = 64;
    __shared__ float Qst[HDIM][BM];
    __shared__ float KP [HDIM * BN];
    __shared__ float Vs [BN][HDIM];

    int qb = blockIdx.x, h = blockIdx.y, b = blockIdx.z;
    int tid = threadIdx.x;
    int tx = tid & 15;
    int ty = tid >> 4;
    const float scale = 0.125f;
    size_t base = (size_t)b * SEQ * DIM + (size_t)h * HDIM;

    #pragma unroll
    for (int p = 0; p < 4; p++) {
        int r = p * 16 + (tid >> 4);
        int c = (tid & 15) << 2;
        float4 q4 = *reinterpret_cast<const float4*>(Q + base + (size_t)(qb * 64 + r) * DIM + c);
        Qst[c + 0][r] = q4.x * scale; Qst[c + 1][r] = q4.y * scale;
        Qst[c + 2][r] = q4.z * scale; Qst[c + 3][r] = q4.w * scale;
    }

    float o_acc[4][4];
    float m_i[4], l_i[4];
    #pragma unroll
    for (int i = 0; i < 4; i++) {
        m_i[i] = -CUDART_INF_F; l_i[i] = 0.0f;
        #pragma unroll
        for (int j = 0; j < 4; j++) o_acc[i][j] = 0.0f;
    }

    for (int kb = 0; kb <= qb; kb++) {
        __syncthreads();
        #pragma unroll
        for (int p = 0; p < 4; p++) {
            int r = p * 16 + (tid >> 4);
            int c = (tid & 15) << 2;
            const float* kg = K + base + (size_t)(kb * 64 + r) * DIM + c;
            const float* vg = V + base + (size_t)(kb * 64 + r) * DIM + c;
            float4 k4 = *reinterpret_cast<const float4*>(kg);
            float4 v4 = *reinterpret_cast<const float4*>(vg);
            KP[(c + 0) * BM + r] = k4.x; KP[(c + 1) * BM + r] = k4.y;
            KP[(c + 2) * BM + r] = k4.z; KP[(c + 3) * BM + r] = k4.w;
            *reinterpret_cast<float4*>(&Vs[r][c]) = v4;
        }
        __syncthreads();

        float s[4][4];
        #pragma unroll
        for (int i = 0; i < 4; i++)
            #pragma unroll
            for (int j = 0; j < 4; j++) s[i][j] = 0.0f;
        #pragma unroll 8
        for (int d = 0; d < HDIM; d++) {
            float a[4], bb[4];
            *reinterpret_cast<float4*>(a)  = *reinterpret_cast<float4*>(&Qst[d][ty * 4]);
            *reinterpret_cast<float4*>(bb) = *reinterpret_cast<float4*>(&KP[d * BM + tx * 4]);
            #pragma unroll
            for (int i = 0; i < 4; i++)
                #pragma unroll
                for (int j = 0; j < 4; j++) s[i][j] = fmaf(a[i], bb[j], s[i][j]);
        }

        if (kb == qb) {
            #pragma unroll
            for (int i = 0; i < 4; i++)
                #pragma unroll
                for (int j = 0; j < 4; j++)
                    if (tx * 4 + j > ty * 4 + i) s[i][j] = -CUDART_INF_F;
        }

        float alpha[4];
        #pragma unroll
        for (int i = 0; i < 4; i++) {
            float rm = fmaxf(fmaxf(s[i][0], s[i][1]), fmaxf(s[i][2], s[i][3]));
            #pragma unroll
            for (int o = 8; o > 0; o >>= 1) rm = fmaxf(rm, __shfl_xor_sync(0xFFFFFFFFu, rm, o));
            float mn = fmaxf(m_i[i], rm);
            alpha[i] = __expf(m_i[i] - mn);
            m_i[i] = mn;
            float rs = 0.0f;
            #pragma unroll
            for (int j = 0; j < 4; j++) {
                s[i][j] = __expf(s[i][j] - mn);
                rs += s[i][j];
            }
            #pragma unroll
            for (int o = 8; o > 0; o >>= 1) rs += __shfl_xor_sync(0xFFFFFFFFu, rs, o);
            l_i[i] = l_i[i] * alpha[i] + rs;
        }

        __syncthreads();
        #pragma unroll
        for (int i = 0; i < 4; i++)
            #pragma unroll
            for (int j = 0; j < 4; j++)
                KP[(ty * 4 + i) * BN + tx * 4 + j] = s[i][j];
        __syncthreads();

        #pragma unroll
        for (int i = 0; i < 4; i++)
            #pragma unroll
            for (int j = 0; j < 4; j++) o_acc[i][j] *= alpha[i];
        #pragma unroll 8
        for (int n = 0; n < BN; n++) {
            float p[4], vv[4];
            #pragma unroll
            for (int i = 0; i < 4; i++) p[i] = KP[(ty * 4 + i) * BN + n];
            *reinterpret_cast<float4*>(vv) = *reinterpret_cast<float4*>(&Vs[n][tx * 4]);
            #pragma unroll
            for (int i = 0; i < 4; i++)
                #pragma unroll
                for (int j = 0; j < 4; j++) o_acc[i][j] = fmaf(p[i], vv[j], o_acc[i][j]);
        }
    }

    #pragma unroll
    for (int i = 0; i < 4; i++) {
        float inv = 1.0f / l_i[i];
        size_t row = (size_t)(qb * 64 + ty * 4 + i);
        float* og = O + base + row * DIM + tx * 4;
        #pragma unroll
        for (int j = 0; j < 4; j++) og[j] = o_acc[i][j] * inv;
    }
}

// ---------------- SiLU(gate) * up ----------------
__global__ void silu_mul_kernel(float* __restrict__ gate, const float* __restrict__ up, int n4) {
    int i = blockIdx.x * blockDim.x + threadIdx.x;
    if (i >= n4) return;
    float4 g = reinterpret_cast<float4*>(gate)[i];
    float4 u = reinterpret_cast<const float4*>(up)[i];
    float4 r;
    r.x = g.x / (1.0f + __expf(-g.x)) * u.x;
    r.y = g.y / (1.0f + __expf(-g.y)) * u.y;
    r.z = g.z / (1.0f + __expf(-g.z)) * u.z;
    r.w = g.w / (1.0f + __expf(-g.w)) * u.w;
    reinterpret_cast<float4*>(gate)[i] = r;
}

// ---------------- launch ----------------
extern "C" void kernel_launch(void* const* d_in, const int* in_sizes, int n_in,
                              void* d_out, int out_size) {
    const float* x     = (const float*)d_in[0];
    const float* wq    = (const float*)d_in[1];
    const float* wk    = (const float*)d_in[2];
    const float* wv    = (const float*)d_in[3];
    const float* wo    = (const float*)d_in[4];
    const float* wgate = (const float*)d_in[5];
    const float* wup   = (const float*)d_in[6];
    const float* wdown = (const float*)d_in[7];
    const float* n1w   = (const float*)d_in[8];
    const float* n2w   = (const float*)d_in[9];
    float* out = (float*)d_out;

    float *h, *q, *k, *v, *att, *x2, *h2, *gate, *up;
    cudaGetSymbolAddress((void**)&h,    g_h);
    cudaGetSymbolAddress((void**)&q,    g_q);
    cudaGetSymbolAddress((void**)&k,    g_k);
    cudaGetSymbolAddress((void**)&v,    g_v);
    cudaGetSymbolAddress((void**)&att,  g_att);
    cudaGetSymbolAddress((void**)&x2,   g_x2);
    cudaGetSymbolAddress((void**)&h2,   g_h2);
    cudaGetSymbolAddress((void**)&gate, g_gate);
    cudaGetSymbolAddress((void**)&up,   g_up);

    rmsnorm_kernel<<<NTOK, 256>>>(x, n1w, h);

    dim3 g1(DIM / 128, NTOK / 128);
    gemm_tf32<<<g1, 256>>>(h, wq, nullptr, q, NTOK, DIM, DIM);
    gemm_tf32<<<g1, 256>>>(h, wk, nullptr, k, NTOK, DIM, DIM);
    gemm_tf32<<<g1, 256>>>(h, wv, nullptr, v, NTOK, DIM, DIM);

    dim3 ga(SEQ / 64, NHEADS, BATCH);
    attn_kernel<<<ga, 256>>>(q, k, v, att);

    gemm_tf32<<<g1, 256>>>(att, wo, x, x2, NTOK, DIM, DIM);

    rmsnorm_kernel<<<NTOK, 256>>>(x2, n2w, h2);

    dim3 g2(HIDDEN / 128, NTOK / 128);
    gemm_tf32<<<g2, 256>>>(h2, wgate, nullptr, gate, NTOK, HIDDEN, DIM);
    gemm_tf32<<<g2, 256>>>(h2, wup,   nullptr, up,   NTOK, HIDDEN, DIM);

    int n4 = NTOK * HIDDEN / 4;
    silu_mul_kernel<<<(n4 + 255) / 256, 256>>>(gate, up, n4);

    gemm_tf32<<<g1, 256>>>(gate, wdown, x2, out, NTOK, DIM, HIDDEN);
}

// round 3
// speedup vs baseline: 2.3453x; 1.0961x over previous
#include <cuda_runtime.h>
#include <math.h>
#include <math_constants.h>

#define DIM     1024
#define NHEADS  16
#define HDIM    64
#define HIDDEN  4096
#define BATCH   2
#define SEQ     2048
#define NTOK    (BATCH * SEQ)
#define EPS     1e-5f

// ---------------- scratch (static device globals; no allocs) ----------------
__device__ float g_h   [NTOK * DIM];
__device__ float g_q   [NTOK * DIM];
__device__ float g_k   [NTOK * DIM];
__device__ float g_v   [NTOK * DIM];
__device__ float g_att [NTOK * DIM];
__device__ float g_x2  [NTOK * DIM];
__device__ float g_h2  [NTOK * DIM];
__device__ float g_gate[NTOK * HIDDEN];
__device__ float g_up  [NTOK * HIDDEN];

// ---------------- RMSNorm: one block per token ----------------
__global__ void rmsnorm_kernel(const float* __restrict__ x,
                               const float* __restrict__ w,
                               float* __restrict__ out) {
    int t = blockIdx.x;
    int tid = threadIdx.x;                      // 256 threads
    const float4* xr = reinterpret_cast<const float4*>(x + (size_t)t * DIM);
    float4 v = xr[tid];
    float ss = v.x * v.x + v.y * v.y + v.z * v.z + v.w * v.w;
    #pragma unroll
    for (int o = 16; o > 0; o >>= 1) ss += __shfl_xor_sync(0xFFFFFFFFu, ss, o);
    __shared__ float red[8];
    if ((tid & 31) == 0) red[tid >> 5] = ss;
    __syncthreads();
    if (tid < 8) {
        float s = red[tid];
        #pragma unroll
        for (int o = 4; o > 0; o >>= 1) s += __shfl_xor_sync(0xFFu, s, o);
        if (tid == 0) red[0] = s;
    }
    __syncthreads();
    float scale = rsqrtf(red[0] * (1.0f / DIM) + EPS);
    float4 wv = reinterpret_cast<const float4*>(w)[tid];
    float4 o4;
    o4.x = v.x * scale * wv.x;
    o4.y = v.y * scale * wv.y;
    o4.z = v.z * scale * wv.z;
    o4.w = v.w * scale * wv.w;
    reinterpret_cast<float4*>(out + (size_t)t * DIM)[tid] = o4;
}

// ---------------- cp.async helpers ----------------
__device__ __forceinline__ void cp16(unsigned dst, const void* src) {
    asm volatile("cp.async.cg.shared.global [%0], [%1], 16;\n" :: "r"(dst), "l"(src));
}
__device__ __forceinline__ void cp_commit() {
    asm volatile("cp.async.commit_group;\n");
}
template <int N>
__device__ __forceinline__ void cp_wait() {
    asm volatile("cp.async.wait_group %0;\n" :: "n"(N));
}
__device__ __forceinline__ unsigned smem_u32(const void* p) {
    return (unsigned)__cvta_generic_to_shared(p);
}

// ---------------- tf32 tensor-core GEMM (NT): C = A B^T (+ res) -------------
// A: [M,K] row-major, B: [N,K] row-major. 128x128 block tile, BK=16,
// 8 warps (2x4), warp tile 64x32, mma.sync.m16n8k8.tf32.
// 2-stage cp.async pipeline; raw fp32 bits fed as tf32 (HW truncates mantissa).
__global__ __launch_bounds__(256)
void gemm_tf32(const float* __restrict__ A, const float* __restrict__ B,
               const float* __restrict__ res, float* __restrict__ C,
               int M, int N, int K) {
    constexpr int BM = 128, BN = 128, BK = 16, LDA = 20;  // 20-word rows: conflict-free
    __shared__ unsigned As[2][BM * LDA];
    __shared__ unsigned Bs[2][BN * LDA];

    int tid  = threadIdx.x;
    int lane = tid & 31;
    int wid  = tid >> 5;
    int wm = (wid & 1) * 64;
    int wn = (wid >> 1) * 32;
    int m0 = blockIdx.y * BM;
    int n0 = blockIdx.x * BN;

    float acc[4][4][4];
    #pragma unroll
    for (int i = 0; i < 4; i++)
        #pragma unroll
        for (int j = 0; j < 4; j++)
            #pragma unroll
            for (int c = 0; c < 4; c++) acc[i][j][c] = 0.0f;

    int lr = tid >> 2;            // 0..63
    int lc = (tid & 3) << 2;      // 0,4,8,12
    const float* Ag = A + (size_t)(m0 + lr) * K + lc;
    const float* Bg = B + (size_t)(n0 + lr) * K + lc;
    size_t rowstep = (size_t)64 * K;

    // per-thread smem dst addresses (two row halves each for A and B)
    unsigned dstA0 = smem_u32(&As[0][(lr +  0) * LDA + lc]);
    unsigned dstA1 = smem_u32(&As[0][(lr + 64) * LDA + lc]);
    unsigned dstB0 = smem_u32(&Bs[0][(lr +  0) * LDA + lc]);
    unsigned dstB1 = smem_u32(&Bs[0][(lr + 64) * LDA + lc]);
    const unsigned stgA = smem_u32(&As[1][0]) - smem_u32(&As[0][0]);
    const unsigned stgB = smem_u32(&Bs[1][0]) - smem_u32(&Bs[0][0]);

    int NT = K / BK;

    // prologue: stage 0
    cp16(dstA0, Ag);           cp16(dstA1, Ag + rowstep);
    cp16(dstB0, Bg);           cp16(dstB1, Bg + rowstep);
    cp_commit();

    for (int it = 0; it < NT; it++) {
        cp_wait<0>();          // stage it landed
        __syncthreads();       // everyone done computing stage it%2's previous contents

        if (it + 1 < NT) {     // issue stage it+1 (overlaps compute below)
            int koff = (it + 1) * BK;
            unsigned s = ((it + 1) & 1);
            cp16(dstA0 + s * stgA, Ag + koff);
            cp16(dstA1 + s * stgA, Ag + rowstep + koff);
            cp16(dstB0 + s * stgB, Bg + koff);
            cp16(dstB1 + s * stgB, Bg + rowstep + koff);
            cp_commit();
        }

        const unsigned* Ast = As[it & 1];
        const unsigned* Bst = Bs[it & 1];
        #pragma unroll
        for (int ks = 0; ks < 2; ks++) {
            int kk = ks * 8;
            unsigned af[4][4], bf[4][2];
            #pragma unroll
            for (int mi = 0; mi < 4; mi++) {
                int m = wm + mi * 16 + (lane >> 2);
                af[mi][0] = Ast[m * LDA + kk + (lane & 3)];
                af[mi][1] = Ast[(m + 8) * LDA + kk + (lane & 3)];
                af[mi][2] = Ast[m * LDA + kk + 4 + (lane & 3)];
                af[mi][3] = Ast[(m + 8) * LDA + kk + 4 + (lane & 3)];
            }
            #pragma unroll
            for (int ni = 0; ni < 4; ni++) {
                int n = wn + ni * 8 + (lane >> 2);
                bf[ni][0] = Bst[n * LDA + kk + (lane & 3)];
                bf[ni][1] = Bst[n * LDA + kk + 4 + (lane & 3)];
            }
            #pragma unroll
            for (int mi = 0; mi < 4; mi++)
                #pragma unroll
                for (int ni = 0; ni < 4; ni++)
                    asm volatile(
                        "mma.sync.aligned.m16n8k8.row.col.f32.tf32.tf32.f32 "
                        "{%0,%1,%2,%3}, {%4,%5,%6,%7}, {%8,%9}, {%0,%1,%2,%3};"
                        : "+f"(acc[mi][ni][0]), "+f"(acc[mi][ni][1]),
                          "+f"(acc[mi][ni][2]), "+f"(acc[mi][ni][3])
                        : "r"(af[mi][0]), "r"(af[mi][1]), "r"(af[mi][2]), "r"(af[mi][3]),
                          "r"(bf[ni][0]), "r"(bf[ni][1]));
        }
    }

    // epilogue
    int gr = lane >> 2;
    int gc = (lane & 3) * 2;
    #pragma unroll
    for (int mi = 0; mi < 4; mi++) {
        #pragma unroll
        for (int ni = 0; ni < 4; ni++) {
            size_t row = (size_t)(m0 + wm + mi * 16 + gr);
            size_t col = (size_t)(n0 + wn + ni * 8 + gc);
            float2 v0 = make_float2(acc[mi][ni][0], acc[mi][ni][1]);
            float2 v1 = make_float2(acc[mi][ni][2], acc[mi][ni][3]);
            if (res) {
                float2 r0 = *reinterpret_cast<const float2*>(res + row * N + col);
                float2 r1 = *reinterpret_cast<const float2*>(res + (row + 8) * N + col);
                v0.x += r0.x; v0.y += r0.y; v1.x += r1.x; v1.y += r1.y;
            }
            *reinterpret_cast<float2*>(C + row * N + col) = v0;
            *reinterpret_cast<float2*>(C + (row + 8) * N + col) = v1;
        }
    }
}

// ---------------- Causal flash attention (fp32) ----------------
__global__ __launch_bounds__(256)
void attn_kernel(const float* __restrict__ Q, const float* __restrict__ K,
                 const float* __restrict__ V, float* __restrict__ O) {
    constexpr int BM = 64, BN = 64;
    __shared__ float Qst[HDIM][BM];
    __shared__ float KP [HDIM * BN];
    __shared__ float Vs [BN][HDIM];

    int qb = blockIdx.x, h = blockIdx.y, b = blockIdx.z;
    int tid = threadIdx.x;
    int tx = tid & 15;
    int ty = tid >> 4;
    const float scale = 0.125f;
    size_t base = (size_t)b * SEQ * DIM + (size_t)h * HDIM;

    #pragma unroll
    for (int p = 0; p < 4; p++) {
        int r = p * 16 + (tid >> 4);
        int c = (tid & 15) << 2;
        float4 q4 = *reinterpret_cast<const float4*>(Q + base + (size_t)(qb * 64 + r) * DIM + c);
        Qst[c + 0][r] = q4.x * scale; Qst[c + 1][r] = q4.y * scale;
        Qst[c + 2][r] = q4.z * scale; Qst[c + 3][r] = q4.w * scale;
    }

    float o_acc[4][4];
    float m_i[4], l_i[4];
    #pragma unroll
    for (int i = 0; i < 4; i++) {
        m_i[i] = -CUDART_INF_F; l_i[i] = 0.0f;
        #pragma unroll
        for (int j = 0; j < 4; j++) o_acc[i][j] = 0.0f;
    }

    for (int kb = 0; kb <= qb; kb++) {
        __syncthreads();
        #pragma unroll
        for (int p = 0; p < 4; p++) {
            int r = p * 16 + (tid >> 4);
            int c = (tid & 15) << 2;
            const float* kg = K + base + (size_t)(kb * 64 + r) * DIM + c;
            const float* vg = V + base + (size_t)(kb * 64 + r) * DIM + c;
            float4 k4 = *reinterpret_cast<const float4*>(kg);
            float4 v4 = *reinterpret_cast<const float4*>(vg);
            KP[(c + 0) * BM + r] = k4.x; KP[(c + 1) * BM + r] = k4.y;
            KP[(c + 2) * BM + r] = k4.z; KP[(c + 3) * BM + r] = k4.w;
            *reinterpret_cast<float4*>(&Vs[r][c]) = v4;
        }
        __syncthreads();

        float s[4][4];
        #pragma unroll
        for (int i = 0; i < 4; i++)
            #pragma unroll
            for (int j = 0; j < 4; j++) s[i][j] = 0.0f;
        #pragma unroll 8
        for (int d = 0; d < HDIM; d++) {
            float a[4], bb[4];
            *reinterpret_cast<float4*>(a)  = *reinterpret_cast<float4*>(&Qst[d][ty * 4]);
            *reinterpret_cast<float4*>(bb) = *reinterpret_cast<float4*>(&KP[d * BM + tx * 4]);
            #pragma unroll
            for (int i = 0; i < 4; i++)
                #pragma unroll
                for (int j = 0; j < 4; j++) s[i][j] = fmaf(a[i], bb[j], s[i][j]);
        }

        if (kb == qb) {
            #pragma unroll
            for (int i = 0; i < 4; i++)
                #pragma unroll
                for (int j = 0; j < 4; j++)
                    if (tx * 4 + j > ty * 4 + i) s[i][j] = -CUDART_INF_F;
        }

        float alpha[4];
        #pragma unroll
        for (int i = 0; i < 4; i++) {
            float rm = fmaxf(fmaxf(s[i][0], s[i][1]), fmaxf(s[i][2], s[i][3]));
            #pragma unroll
            for (int o = 8; o > 0; o >>= 1) rm = fmaxf(rm, __shfl_xor_sync(0xFFFFFFFFu, rm, o));
            float mn = fmaxf(m_i[i], rm);
            alpha[i] = __expf(m_i[i] - mn);
            m_i[i] = mn;
            float rs = 0.0f;
            #pragma unroll
            for (int j = 0; j < 4; j++) {
                s[i][j] = __expf(s[i][j] - mn);
                rs += s[i][j];
            }
            #pragma unroll
            for (int o = 8; o > 0; o >>= 1) rs += __shfl_xor_sync(0xFFFFFFFFu, rs, o);
            l_i[i] = l_i[i] * alpha[i] + rs;
        }

        __syncthreads();
        #pragma unroll
        for (int i = 0; i < 4; i++)
            #pragma unroll
            for (int j = 0; j < 4; j++)
                KP[(ty * 4 + i) * BN + tx * 4 + j] = s[i][j];
        __syncthreads();

        #pragma unroll
        for (int i = 0; i < 4; i++)
            #pragma unroll
            for (int j = 0; j < 4; j++) o_acc[i][j] *= alpha[i];
        #pragma unroll 8
        for (int n = 0; n < BN; n++) {
            float p[4], vv[4];
            #pragma unroll
            for (int i = 0; i < 4; i++) p[i] = KP[(ty * 4 + i) * BN + n];
            *reinterpret_cast<float4*>(vv) = *reinterpret_cast<float4*>(&Vs[n][tx * 4]);
            #pragma unroll
            for (int i = 0; i < 4; i++)
                #pragma unroll
                for (int j = 0; j < 4; j++) o_acc[i][j] = fmaf(p[i], vv[j], o_acc[i][j]);
        }
    }

    #pragma unroll
    for (int i = 0; i < 4; i++) {
        float inv = 1.0f / l_i[i];
        size_t row = (size_t)(qb * 64 + ty * 4 + i);
        float* og = O + base + row * DIM + tx * 4;
        #pragma unroll
        for (int j = 0; j < 4; j++) og[j] = o_acc[i][j] * inv;
    }
}

// ---------------- SiLU(gate) * up ----------------
__global__ void silu_mul_kernel(float* __restrict__ gate, const float* __restrict__ up, int n4) {
    int i = blockIdx.x * blockDim.x + threadIdx.x;
    if (i >= n4) return;
    float4 g = reinterpret_cast<float4*>(gate)[i];
    float4 u = reinterpret_cast<const float4*>(up)[i];
    float4 r;
    r.x = g.x / (1.0f + __expf(-g.x)) * u.x;
    r.y = g.y / (1.0f + __expf(-g.y)) * u.y;
    r.z = g.z / (1.0f + __expf(-g.z)) * u.z;
    r.w = g.w / (1.0f + __expf(-g.w)) * u.w;
    reinterpret_cast<float4*>(gate)[i] = r;
}

// ---------------- launch ----------------
extern "C" void kernel_launch(void* const* d_in, const int* in_sizes, int n_in,
                              void* d_out, int out_size) {
    const float* x     = (const float*)d_in[0];
    const float* wq    = (const float*)d_in[1];
    const float* wk    = (const float*)d_in[2];
    const float* wv    = (const float*)d_in[3];
    const float* wo    = (const float*)d_in[4];
    const float* wgate = (const float*)d_in[5];
    const float* wup   = (const float*)d_in[6];
    const float* wdown = (const float*)d_in[7];
    const float* n1w   = (const float*)d_in[8];
    const float* n2w   = (const float*)d_in[9];
    float* out = (float*)d_out;

    float *h, *q, *k, *v, *att, *x2, *h2, *gate, *up;
    cudaGetSymbolAddress((void**)&h,    g_h);
    cudaGetSymbolAddress((void**)&q,    g_q);
    cudaGetSymbolAddress((void**)&k,    g_k);
    cudaGetSymbolAddress((void**)&v,    g_v);
    cudaGetSymbolAddress((void**)&att,  g_att);
    cudaGetSymbolAddress((void**)&x2,   g_x2);
    cudaGetSymbolAddress((void**)&h2,   g_h2);
    cudaGetSymbolAddress((void**)&gate, g_gate);
    cudaGetSymbolAddress((void**)&up,   g_up);

    rmsnorm_kernel<<<NTOK, 256>>>(x, n1w, h);

    dim3 g1(DIM / 128, NTOK / 128);
    gemm_tf32<<<g1, 256>>>(h, wq, nullptr, q, NTOK, DIM, DIM);
    gemm_tf32<<<g1, 256>>>(h, wk, nullptr, k, NTOK, DIM, DIM);
    gemm_tf32<<<g1, 256>>>(h, wv, nullptr, v, NTOK, DIM, DIM);

    dim3 ga(SEQ / 64, NHEADS, BATCH);
    attn_kernel<<<ga, 256>>>(q, k, v, att);

    gemm_tf32<<<g1, 256>>>(att, wo, x, x2, NTOK, DIM, DIM);

    rmsnorm_kernel<<<NTOK, 256>>>(x2, n2w, h2);

    dim3 g2(HIDDEN / 128, NTOK / 128);
    gemm_tf32<<<g2, 256>>>(h2, wgate, nullptr, gate, NTOK, HIDDEN, DIM);
    gemm_tf32<<<g2, 256>>>(h2, wup,   nullptr, up,   NTOK, HIDDEN, DIM);

    int n4 = NTOK * HIDDEN / 4;
    silu_mul_kernel<<<(n4 + 255) / 256, 256>>>(gate, up, n4);

    gemm_tf32<<<g1, 256>>>(gate, wdown, x2, out, NTOK, DIM, HIDDEN);
}

// round 5
// speedup vs baseline: 3.2493x; 1.3855x over previous
#include <cuda_runtime.h>
#include <cuda_fp16.h>
#include <math.h>
#include <math_constants.h>
#include <stdint.h>

#define DIM     1024
#define NHEADS  16
#define HDIM    64
#define HIDDEN  4096
#define BATCH   2
#define SEQ     2048
#define NTOK    (BATCH * SEQ)
#define EPS     1e-5f

// ---------------- scratch (static device globals; no allocs) ----------------
__device__ __half g_h   [NTOK * DIM];     // rmsnorm1 out (fp16)
__device__ float  g_q   [NTOK * DIM];
__device__ float  g_k   [NTOK * DIM];
__device__ float  g_v   [NTOK * DIM];
__device__ __half g_att [NTOK * DIM];     // attention out (fp16)
__device__ float  g_x2  [NTOK * DIM];
__device__ __half g_h2  [NTOK * DIM];     // rmsnorm2 out (fp16)
__device__ float  g_gate[NTOK * HIDDEN];
__device__ float  g_up  [NTOK * HIDDEN];
__device__ __half g_act [NTOK * HIDDEN];  // silu(gate)*up (fp16)
// fp16 weight copies
__device__ __half g_wq  [DIM * DIM];
__device__ __half g_wk  [DIM * DIM];
__device__ __half g_wv  [DIM * DIM];
__device__ __half g_wo  [DIM * DIM];
__device__ __half g_wg  [HIDDEN * DIM];
__device__ __half g_wu  [HIDDEN * DIM];
__device__ __half g_wd  [DIM * HIDDEN];

// ---------------- helpers ----------------
__device__ __forceinline__ void cp16(unsigned dst, const void* src) {
    asm volatile("cp.async.cg.shared.global [%0], [%1], 16;\n" :: "r"(dst), "l"(src));
}
__device__ __forceinline__ void cp_commit() {
    asm volatile("cp.async.commit_group;\n");
}
template <int N>
__device__ __forceinline__ void cp_wait() {
    asm volatile("cp.async.wait_group %0;\n" :: "n"(N));
}
__device__ __forceinline__ unsigned smem_u32(const void* p) {
    return (unsigned)__cvta_generic_to_shared(p);
}

// ---------------- fp16 tensor-core GEMM (NT): C = A B^T (+ res) -------------
// A: [M,K] fp16 row-major, B: [N,K] fp16 row-major, C/res: fp32.
// 128x128 tile, BK=32, 8 warps (2x4), warp tile 64x32, mma.m16n8k16,
// ldmatrix fragment loads, 2-stage cp.async pipeline.
// smem rows padded to 40 halves (80B) -> conflict-free ldmatrix.
#define LDH 40

__device__ __forceinline__ void fill_stage_h(unsigned baseA, unsigned baseB,
                                             const __half* A, const __half* B,
                                             int K, int m0, int n0, int kt, int tid) {
    int row = tid >> 2;           // 0..63
    int kc  = tid & 3;            // 0..3 (16B chunks of 8 halves)
    const __half* ag = A + (size_t)(m0 + row) * K + kt * 32 + kc * 8;
    const __half* bg = B + (size_t)(n0 + row) * K + kt * 32 + kc * 8;
    unsigned off  = (unsigned)(row * LDH * 2 + kc * 16);
    unsigned off2 = off + 64 * LDH * 2;
    size_t gstep = (size_t)64 * K;
    cp16(baseA + off,  ag);
    cp16(baseA + off2, ag + gstep);
    cp16(baseB + off,  bg);
    cp16(baseB + off2, bg + gstep);
    cp_commit();
}

__global__ __launch_bounds__(256)
void gemm_fp16(const __half* __restrict__ A, const __half* __restrict__ B,
               const float* __restrict__ res, float* __restrict__ C,
               int M, int N, int K) {
    __shared__ __half As[2][128 * LDH];
    __shared__ __half Bs[2][128 * LDH];

    int tid  = threadIdx.x;
    int lane = tid & 31;
    int wid  = tid >> 5;
    int wm = (wid & 1) * 64;
    int wn = (wid >> 1) * 32;
    int m0 = blockIdx.y * 128;
    int n0 = blockIdx.x * 128;

    float acc[4][4][4];
    #pragma unroll
    for (int i = 0; i < 4; i++)
        #pragma unroll
        for (int j = 0; j < 4; j++)
            #pragma unroll
            for (int c = 0; c < 4; c++) acc[i][j][c] = 0.0f;

    unsigned baseA[2] = { smem_u32(As[0]), smem_u32(As[1]) };
    unsigned baseB[2] = { smem_u32(Bs[0]), smem_u32(Bs[1]) };

    const int NT = K >> 5;   // BK=32

    fill_stage_h(baseA[0], baseB[0], A, B, K, m0, n0, 0, tid);

    // ldmatrix lane addressing: row = lane%16, col halves = (lane/16)*8
    unsigned lrow = (unsigned)(lane & 15);
    unsigned lcolb = (unsigned)((lane >> 4) * 8 * 2);   // byte offset within k16

    for (int it = 0; it < NT; it++) {
        cp_wait<0>();
        __syncthreads();

        if (it + 1 < NT) {
            int s = (it + 1) & 1;
            fill_stage_h(baseA[s], baseB[s], A, B, K, m0, n0, it + 1, tid);
        }

        int st = it & 1;
        #pragma unroll
        for (int ks = 0; ks < 2; ks++) {
            unsigned kbyte = (unsigned)(ks * 16 * 2) + lcolb;
            uint32_t af[4][4], bf[2][4];
            #pragma unroll
            for (int mi = 0; mi < 4; mi++) {
                unsigned addr = baseA[st] + (unsigned)((wm + mi * 16 + lrow) * LDH * 2) + kbyte;
                asm volatile("ldmatrix.sync.aligned.m8n8.x4.shared.b16 {%0,%1,%2,%3}, [%4];"
                             : "=r"(af[mi][0]), "=r"(af[mi][1]), "=r"(af[mi][2]), "=r"(af[mi][3])
                             : "r"(addr));
            }
            #pragma unroll
            for (int nb = 0; nb < 2; nb++) {
                unsigned addr = baseB[st] + (unsigned)((wn + nb * 16 + lrow) * LDH * 2) + kbyte;
                asm volatile("ldmatrix.sync.aligned.m8n8.x4.shared.b16 {%0,%1,%2,%3}, [%4];"
                             : "=r"(bf[nb][0]), "=r"(bf[nb][1]), "=r"(bf[nb][2]), "=r"(bf[nb][3])
                             : "r"(addr));
            }
            #pragma unroll
            for (int mi = 0; mi < 4; mi++) {
                #pragma unroll
                for (int ni = 0; ni < 4; ni++) {
                    int nb = ni >> 1, blk = ni & 1;
                    asm volatile(
                        "mma.sync.aligned.m16n8k16.row.col.f32.f16.f16.f32 "
                        "{%0,%1,%2,%3}, {%4,%5,%6,%7}, {%8,%9}, {%0,%1,%2,%3};"
                        : "+f"(acc[mi][ni][0]), "+f"(acc[mi][ni][1]),
                          "+f"(acc[mi][ni][2]), "+f"(acc[mi][ni][3])
                        : "r"(af[mi][0]), "r"(af[mi][1]), "r"(af[mi][2]), "r"(af[mi][3]),
                          "r"(bf[nb][blk]), "r"(bf[nb][blk + 2]));
                }
            }
        }
        __syncthreads();
    }

    // epilogue: m16n8 frag -> c0/c1 at (row, 2c), c2/c3 at row+8
    int gr = lane >> 2;
    int gc = (lane & 3) * 2;
    #pragma unroll
    for (int mi = 0; mi < 4; mi++) {
        #pragma unroll
        for (int ni = 0; ni < 4; ni++) {
            size_t row = (size_t)(m0 + wm + mi * 16 + gr);
            size_t col = (size_t)(n0 + wn + ni * 8 + gc);
            float2 v0 = make_float2(acc[mi][ni][0], acc[mi][ni][1]);
            float2 v1 = make_float2(acc[mi][ni][2], acc[mi][ni][3]);
            if (res) {
                float2 r0 = *reinterpret_cast<const float2*>(res + row * N + col);
                float2 r1 = *reinterpret_cast<const float2*>(res + (row + 8) * N + col);
                v0.x += r0.x; v0.y += r0.y; v1.x += r1.x; v1.y += r1.y;
            }
            *reinterpret_cast<float2*>(C + row * N + col) = v0;
            *reinterpret_cast<float2*>(C + (row + 8) * N + col) = v1;
        }
    }
}

// ---------------- weight fp32 -> fp16 (RNE) ----------------
__global__ void cvt_fp16_kernel(const float* __restrict__ in, __half* __restrict__ out, int n4) {
    int i = blockIdx.x * blockDim.x + threadIdx.x;
    if (i >= n4) return;
    float4 v = reinterpret_cast<const float4*>(in)[i];
    __half2 h0 = __floats2half2_rn(v.x, v.y);
    __half2 h1 = __floats2half2_rn(v.z, v.w);
    reinterpret_cast<__half2*>(out)[i * 2]     = h0;
    reinterpret_cast<__half2*>(out)[i * 2 + 1] = h1;
}

// ---------------- RMSNorm: one block per token, fp16 out ----------------
__global__ void rmsnorm_kernel(const float* __restrict__ x,
                               const float* __restrict__ w,
                               __half* __restrict__ out) {
    int t = blockIdx.x;
    int tid = threadIdx.x;                      // 256 threads
    const float4* xr = reinterpret_cast<const float4*>(x + (size_t)t * DIM);
    float4 v = xr[tid];
    float ss = v.x * v.x + v.y * v.y + v.z * v.z + v.w * v.w;
    #pragma unroll
    for (int o = 16; o > 0; o >>= 1) ss += __shfl_xor_sync(0xFFFFFFFFu, ss, o);
    __shared__ float red[8];
    if ((tid & 31) == 0) red[tid >> 5] = ss;
    __syncthreads();
    if (tid < 8) {
        float s = red[tid];
        #pragma unroll
        for (int o = 4; o > 0; o >>= 1) s += __shfl_xor_sync(0xFFu, s, o);
        if (tid == 0) red[0] = s;
    }
    __syncthreads();
    float scale = rsqrtf(red[0] * (1.0f / DIM) + EPS);
    float4 wv = reinterpret_cast<const float4*>(w)[tid];
    __half2 h0 = __floats2half2_rn(v.x * scale * wv.x, v.y * scale * wv.y);
    __half2 h1 = __floats2half2_rn(v.z * scale * wv.z, v.w * scale * wv.w);
    __half2* op = reinterpret_cast<__half2*>(out + (size_t)t * DIM) + tid * 2;
    op[0] = h0; op[1] = h1;
}

// ---------------- Causal flash attention (fp32 math, fp16 out) --------------
__global__ __launch_bounds__(256)
void attn_kernel(const float* __restrict__ Q, const float* __restrict__ K,
                 const float* __restrict__ V, __half* __restrict__ O) {
    constexpr int BM = 64, BN = 64;
    __shared__ float Qst[HDIM][BM];
    __shared__ float KP [HDIM * BN];
    __shared__ float Vs [BN][HDIM];

    int qb = blockIdx.x, h = blockIdx.y, b = blockIdx.z;
    int tid = threadIdx.x;
    int tx = tid & 15;
    int ty = tid >> 4;
    const float scale = 0.125f;
    size_t base = (size_t)b * SEQ * DIM + (size_t)h * HDIM;

    #pragma unroll
    for (int p = 0; p < 4; p++) {
        int r = p * 16 + (tid >> 4);
        int c = (tid & 15) << 2;
        float4 q4 = *reinterpret_cast<const float4*>(Q + base + (size_t)(qb * 64 + r) * DIM + c);
        Qst[c + 0][r] = q4.x * scale; Qst[c + 1][r] = q4.y * scale;
        Qst[c + 2][r] = q4.z * scale; Qst[c + 3][r] = q4.w * scale;
    }

    float o_acc[4][4];
    float m_i[4], l_i[4];
    #pragma unroll
    for (int i = 0; i < 4; i++) {
        m_i[i] = -CUDART_INF_F; l_i[i] = 0.0f;
        #pragma unroll
        for (int j = 0; j < 4; j++) o_acc[i][j] = 0.0f;
    }

    for (int kb = 0; kb <= qb; kb++) {
        __syncthreads();
        #pragma unroll
        for (int p = 0; p < 4; p++) {
            int r = p * 16 + (tid >> 4);
            int c = (tid & 15) << 2;
            const float* kg = K + base + (size_t)(kb * 64 + r) * DIM + c;
            const float* vg = V + base + (size_t)(kb * 64 + r) * DIM + c;
            float4 k4 = *reinterpret_cast<const float4*>(kg);
            float4 v4 = *reinterpret_cast<const float4*>(vg);
            KP[(c + 0) * BM + r] = k4.x; KP[(c + 1) * BM + r] = k4.y;
            KP[(c + 2) * BM + r] = k4.z; KP[(c + 3) * BM + r] = k4.w;
            *reinterpret_cast<float4*>(&Vs[r][c]) = v4;
        }
        __syncthreads();

        float s[4][4];
        #pragma unroll
        for (int i = 0; i < 4; i++)
            #pragma unroll
            for (int j = 0; j < 4; j++) s[i][j] = 0.0f;
        #pragma unroll 8
        for (int d = 0; d < HDIM; d++) {
            float a[4], bb[4];
            *reinterpret_cast<float4*>(a)  = *reinterpret_cast<float4*>(&Qst[d][ty * 4]);
            *reinterpret_cast<float4*>(bb) = *reinterpret_cast<float4*>(&KP[d * BM + tx * 4]);
            #pragma unroll
            for (int i = 0; i < 4; i++)
                #pragma unroll
                for (int j = 0; j < 4; j++) s[i][j] = fmaf(a[i], bb[j], s[i][j]);
        }

        if (kb == qb) {
            #pragma unroll
            for (int i = 0; i < 4; i++)
                #pragma unroll
                for (int j = 0; j < 4; j++)
                    if (tx * 4 + j > ty * 4 + i) s[i][j] = -CUDART_INF_F;
        }

        float alpha[4];
        #pragma unroll
        for (int i = 0; i < 4; i++) {
            float rm = fmaxf(fmaxf(s[i][0], s[i][1]), fmaxf(s[i][2], s[i][3]));
            #pragma unroll
            for (int o = 8; o > 0; o >>= 1) rm = fmaxf(rm, __shfl_xor_sync(0xFFFFFFFFu, rm, o));
            float mn = fmaxf(m_i[i], rm);
            alpha[i] = __expf(m_i[i] - mn);
            m_i[i] = mn;
            float rs = 0.0f;
            #pragma unroll
            for (int j = 0; j < 4; j++) {
                s[i][j] = __expf(s[i][j] - mn);
                rs += s[i][j];
            }
            #pragma unroll
            for (int o = 8; o > 0; o >>= 1) rs += __shfl_xor_sync(0xFFFFFFFFu, rs, o);
            l_i[i] = l_i[i] * alpha[i] + rs;
        }

        __syncthreads();
        #pragma unroll
        for (int i = 0; i < 4; i++)
            #pragma unroll
            for (int j = 0; j < 4; j++)
                KP[(ty * 4 + i) * BN + tx * 4 + j] = s[i][j];
        __syncthreads();

        #pragma unroll
        for (int i = 0; i < 4; i++)
            #pragma unroll
            for (int j = 0; j < 4; j++) o_acc[i][j] *= alpha[i];
        #pragma unroll 8
        for (int n = 0; n < BN; n++) {
            float p[4], vv[4];
            #pragma unroll
            for (int i = 0; i < 4; i++) p[i] = KP[(ty * 4 + i) * BN + n];
            *reinterpret_cast<float4*>(vv) = *reinterpret_cast<float4*>(&Vs[n][tx * 4]);
            #pragma unroll
            for (int i = 0; i < 4; i++)
                #pragma unroll
                for (int j = 0; j < 4; j++) o_acc[i][j] = fmaf(p[i], vv[j], o_acc[i][j]);
        }
    }

    #pragma unroll
    for (int i = 0; i < 4; i++) {
        float inv = 1.0f / l_i[i];
        size_t row = (size_t)(qb * 64 + ty * 4 + i);
        __half2* og = reinterpret_cast<__half2*>(O + base + row * DIM + tx * 4);
        og[0] = __floats2half2_rn(o_acc[i][0] * inv, o_acc[i][1] * inv);
        og[1] = __floats2half2_rn(o_acc[i][2] * inv, o_acc[i][3] * inv);
    }
}

// ---------------- SiLU(gate) * up -> fp16 act ----------------
__global__ void silu_mul_kernel(const float* __restrict__ gate, const float* __restrict__ up,
                                __half* __restrict__ act, int n4) {
    int i = blockIdx.x * blockDim.x + threadIdx.x;
    if (i >= n4) return;
    float4 g = reinterpret_cast<const float4*>(gate)[i];
    float4 u = reinterpret_cast<const float4*>(up)[i];
    float rx = g.x / (1.0f + __expf(-g.x)) * u.x;
    float ry = g.y / (1.0f + __expf(-g.y)) * u.y;
    float rz = g.z / (1.0f + __expf(-g.z)) * u.z;
    float rw = g.w / (1.0f + __expf(-g.w)) * u.w;
    reinterpret_cast<__half2*>(act)[i * 2]     = __floats2half2_rn(rx, ry);
    reinterpret_cast<__half2*>(act)[i * 2 + 1] = __floats2half2_rn(rz, rw);
}

// ---------------- launch ----------------
extern "C" void kernel_launch(void* const* d_in, const int* in_sizes, int n_in,
                              void* d_out, int out_size) {
    const float* x     = (const float*)d_in[0];
    const float* wq    = (const float*)d_in[1];
    const float* wk    = (const float*)d_in[2];
    const float* wv    = (const float*)d_in[3];
    const float* wo    = (const float*)d_in[4];
    const float* wgate = (const float*)d_in[5];
    const float* wup   = (const float*)d_in[6];
    const float* wdown = (const float*)d_in[7];
    const float* n1w   = (const float*)d_in[8];
    const float* n2w   = (const float*)d_in[9];
    float* out = (float*)d_out;

    float *q, *k, *v, *x2, *gate, *up;
    __half *h, *att, *h2, *act;
    __half *cwq, *cwk, *cwv, *cwo, *cwg, *cwu, *cwd;
    cudaGetSymbolAddress((void**)&h,    g_h);
    cudaGetSymbolAddress((void**)&q,    g_q);
    cudaGetSymbolAddress((void**)&k,    g_k);
    cudaGetSymbolAddress((void**)&v,    g_v);
    cudaGetSymbolAddress((void**)&att,  g_att);
    cudaGetSymbolAddress((void**)&x2,   g_x2);
    cudaGetSymbolAddress((void**)&h2,   g_h2);
    cudaGetSymbolAddress((void**)&gate, g_gate);
    cudaGetSymbolAddress((void**)&up,   g_up);
    cudaGetSymbolAddress((void**)&act,  g_act);
    cudaGetSymbolAddress((void**)&cwq,  g_wq);
    cudaGetSymbolAddress((void**)&cwk,  g_wk);
    cudaGetSymbolAddress((void**)&cwv,  g_wv);
    cudaGetSymbolAddress((void**)&cwo,  g_wo);
    cudaGetSymbolAddress((void**)&cwg,  g_wg);
    cudaGetSymbolAddress((void**)&cwu,  g_wu);
    cudaGetSymbolAddress((void**)&cwd,  g_wd);

    // weight conversion (RNE fp16)
    int nw1 = DIM * DIM / 4, nw2 = HIDDEN * DIM / 4;
    cvt_fp16_kernel<<<(nw1 + 255) / 256, 256>>>(wq,    cwq, nw1);
    cvt_fp16_kernel<<<(nw1 + 255) / 256, 256>>>(wk,    cwk, nw1);
    cvt_fp16_kernel<<<(nw1 + 255) / 256, 256>>>(wv,    cwv, nw1);
    cvt_fp16_kernel<<<(nw1 + 255) / 256, 256>>>(wo,    cwo, nw1);
    cvt_fp16_kernel<<<(nw2 + 255) / 256, 256>>>(wgate, cwg, nw2);
    cvt_fp16_kernel<<<(nw2 + 255) / 256, 256>>>(wup,   cwu, nw2);
    cvt_fp16_kernel<<<(nw2 + 255) / 256, 256>>>(wdown, cwd, nw2);

    rmsnorm_kernel<<<NTOK, 256>>>(x, n1w, h);

    dim3 g1(DIM / 128, NTOK / 128);
    gemm_fp16<<<g1, 256>>>(h, cwq, nullptr, q, NTOK, DIM, DIM);
    gemm_fp16<<<g1, 256>>>(h, cwk, nullptr, k, NTOK, DIM, DIM);
    gemm_fp16<<<g1, 256>>>(h, cwv, nullptr, v, NTOK, DIM, DIM);

    dim3 ga(SEQ / 64, NHEADS, BATCH);
    attn_kernel<<<ga, 256>>>(q, k, v, att);

    gemm_fp16<<<g1, 256>>>(att, cwo, x, x2, NTOK, DIM, DIM);

    rmsnorm_kernel<<<NTOK, 256>>>(x2, n2w, h2);

    dim3 g2(HIDDEN / 128, NTOK / 128);
    gemm_fp16<<<g2, 256>>>(h2, cwg, nullptr, gate, NTOK, HIDDEN, DIM);
    gemm_fp16<<<g2, 256>>>(h2, cwu, nullptr, up,   NTOK, HIDDEN, DIM);

    int n4 = NTOK * HIDDEN / 4;
    silu_mul_kernel<<<(n4 + 255) / 256, 256>>>(gate, up, act, n4);

    gemm_fp16<<<g1, 256>>>(act, cwd, x2, out, NTOK, DIM, HIDDEN);
}

// round 6
// speedup vs baseline: 6.2570x; 1.9256x over previous
#include <cuda_runtime.h>
#include <cuda_fp16.h>
#include <math.h>
#include <math_constants.h>
#include <stdint.h>

#define DIM     1024
#define NHEADS  16
#define HDIM    64
#define HIDDEN  4096
#define BATCH   2
#define SEQ     2048
#define NTOK    (BATCH * SEQ)
#define EPS     1e-5f

// ---------------- scratch (static device globals; no allocs) ----------------
__device__ __half g_h   [NTOK * DIM];         // rmsnorm1 out
__device__ __half g_qkv [NTOK * 3 * DIM];     // fused qkv out (fp16)
__device__ __half g_att [NTOK * DIM];         // attention out
__device__ float  g_x2  [NTOK * DIM];         // residual after attention
__device__ __half g_h2  [NTOK * DIM];         // rmsnorm2 out
__device__ float  g_gu  [NTOK * 2 * HIDDEN];  // fused gate|up out (fp32)
__device__ __half g_act [NTOK * HIDDEN];      // silu(gate)*up
// fp16 weights: wqkv = [wq;wk;wv] rows, wgu = [wgate;wup] rows
__device__ __half g_wqkv[3 * DIM * DIM];
__device__ __half g_wo  [DIM * DIM];
__device__ __half g_wgu [2 * HIDDEN * DIM];
__device__ __half g_wd  [DIM * HIDDEN];

// ---------------- helpers ----------------
__device__ __forceinline__ void cp16(unsigned dst, const void* src) {
    asm volatile("cp.async.cg.shared.global [%0], [%1], 16;\n" :: "r"(dst), "l"(src));
}
__device__ __forceinline__ void cp_commit() {
    asm volatile("cp.async.commit_group;\n");
}
template <int N>
__device__ __forceinline__ void cp_wait() {
    asm volatile("cp.async.wait_group %0;\n" :: "n"(N));
}
__device__ __forceinline__ unsigned smem_u32(const void* p) {
    return (unsigned)__cvta_generic_to_shared(p);
}
__device__ __forceinline__ float ex2f(float x) {
    float r; asm("ex2.approx.f32 %0, %1;" : "=f"(r) : "f"(x)); return r;
}
__device__ __forceinline__ uint32_t packh2(float a, float b) {
    __half2 h = __floats2half2_rn(a, b);
    return *reinterpret_cast<uint32_t*>(&h);
}
#define LDMX4(r0, r1, r2, r3, addr) \
    asm volatile("ldmatrix.sync.aligned.m8n8.x4.shared.b16 {%0,%1,%2,%3}, [%4];" \
                 : "=r"(r0), "=r"(r1), "=r"(r2), "=r"(r3) : "r"(addr))
#define LDMX4T(r0, r1, r2, r3, addr) \
    asm volatile("ldmatrix.sync.aligned.m8n8.x4.trans.shared.b16 {%0,%1,%2,%3}, [%4];" \
                 : "=r"(r0), "=r"(r1), "=r"(r2), "=r"(r3) : "r"(addr))
#define MMA16816(c, a0, a1, a2, a3, b0, b1) \
    asm volatile("mma.sync.aligned.m16n8k16.row.col.f32.f16.f16.f32 " \
                 "{%0,%1,%2,%3}, {%4,%5,%6,%7}, {%8,%9}, {%0,%1,%2,%3};" \
                 : "+f"((c)[0]), "+f"((c)[1]), "+f"((c)[2]), "+f"((c)[3]) \
                 : "r"(a0), "r"(a1), "r"(a2), "r"(a3), "r"(b0), "r"(b1))

// ---------------- fp16 tensor-core GEMM (NT): C = A B^T (+ res) -------------
// A: [M,K] fp16 row-major (lda=K), B: [N,K] fp16 row-major.
// 128x128 tile, BK=32, 8 warps (2x4), warp tile 64x32, 2-stage cp.async.
#define LDH 40

__device__ __forceinline__ void fill_stage_h(unsigned baseA, unsigned baseB,
                                             const __half* A, const __half* B,
                                             int K, int m0, int n0, int kt, int tid) {
    int row = tid >> 2;
    int kc  = tid & 3;
    const __half* ag = A + (size_t)(m0 + row) * K + kt * 32 + kc * 8;
    const __half* bg = B + (size_t)(n0 + row) * K + kt * 32 + kc * 8;
    unsigned off  = (unsigned)(row * LDH * 2 + kc * 16);
    unsigned off2 = off + 64 * LDH * 2;
    size_t gstep = (size_t)64 * K;
    cp16(baseA + off,  ag);
    cp16(baseA + off2, ag + gstep);
    cp16(baseB + off,  bg);
    cp16(baseB + off2, bg + gstep);
    cp_commit();
}

template<typename OT>
__global__ __launch_bounds__(256)
void gemm_fp16(const __half* __restrict__ A, const __half* __restrict__ B,
               const float* __restrict__ res, OT* __restrict__ C,
               int K, int ldc) {
    __shared__ __half As[2][128 * LDH];
    __shared__ __half Bs[2][128 * LDH];

    int tid  = threadIdx.x;
    int lane = tid & 31;
    int wid  = tid >> 5;
    int wm = (wid & 1) * 64;
    int wn = (wid >> 1) * 32;
    int m0 = blockIdx.y * 128;
    int n0 = blockIdx.x * 128;

    float acc[4][4][4];
    #pragma unroll
    for (int i = 0; i < 4; i++)
        #pragma unroll
        for (int j = 0; j < 4; j++)
            #pragma unroll
            for (int c = 0; c < 4; c++) acc[i][j][c] = 0.0f;

    unsigned baseA[2] = { smem_u32(As[0]), smem_u32(As[1]) };
    unsigned baseB[2] = { smem_u32(Bs[0]), smem_u32(Bs[1]) };

    const int NT = K >> 5;

    fill_stage_h(baseA[0], baseB[0], A, B, K, m0, n0, 0, tid);

    unsigned lrow = (unsigned)(lane & 15);
    unsigned lcolb = (unsigned)((lane >> 4) * 16);

    for (int it = 0; it < NT; it++) {
        cp_wait<0>();
        __syncthreads();

        if (it + 1 < NT) {
            int s = (it + 1) & 1;
            fill_stage_h(baseA[s], baseB[s], A, B, K, m0, n0, it + 1, tid);
        }

        int st = it & 1;
        #pragma unroll
        for (int ks = 0; ks < 2; ks++) {
            unsigned kbyte = (unsigned)(ks * 32) + lcolb;
            uint32_t af[4][4], bf[2][4];
            #pragma unroll
            for (int mi = 0; mi < 4; mi++) {
                unsigned addr = baseA[st] + (unsigned)((wm + mi * 16 + lrow) * LDH * 2) + kbyte;
                LDMX4(af[mi][0], af[mi][1], af[mi][2], af[mi][3], addr);
            }
            #pragma unroll
            for (int nb = 0; nb < 2; nb++) {
                unsigned addr = baseB[st] + (unsigned)((wn + nb * 16 + lrow) * LDH * 2) + kbyte;
                LDMX4(bf[nb][0], bf[nb][1], bf[nb][2], bf[nb][3], addr);
            }
            #pragma unroll
            for (int mi = 0; mi < 4; mi++) {
                #pragma unroll
                for (int ni = 0; ni < 4; ni++) {
                    int nb = ni >> 1, blk = ni & 1;
                    MMA16816(acc[mi][ni], af[mi][0], af[mi][1], af[mi][2], af[mi][3],
                             bf[nb][blk], bf[nb][blk + 2]);
                }
            }
        }
        __syncthreads();
    }

    int gr = lane >> 2;
    int gc = (lane & 3) * 2;
    #pragma unroll
    for (int mi = 0; mi < 4; mi++) {
        #pragma unroll
        for (int ni = 0; ni < 4; ni++) {
            size_t row = (size_t)(m0 + wm + mi * 16 + gr);
            size_t col = (size_t)(n0 + wn + ni * 8 + gc);
            float v[4] = { acc[mi][ni][0], acc[mi][ni][1], acc[mi][ni][2], acc[mi][ni][3] };
            if (res) {
                float2 r0 = *reinterpret_cast<const float2*>(res + row * ldc + col);
                float2 r1 = *reinterpret_cast<const float2*>(res + (row + 8) * ldc + col);
                v[0] += r0.x; v[1] += r0.y; v[2] += r1.x; v[3] += r1.y;
            }
            if (sizeof(OT) == 4) {
                float* Cf = (float*)C;
                *reinterpret_cast<float2*>(Cf + row * ldc + col) = make_float2(v[0], v[1]);
                *reinterpret_cast<float2*>(Cf + (row + 8) * ldc + col) = make_float2(v[2], v[3]);
            } else {
                __half* Ch = (__half*)C;
                *reinterpret_cast<__half2*>(Ch + row * ldc + col) = __floats2half2_rn(v[0], v[1]);
                *reinterpret_cast<__half2*>(Ch + (row + 8) * ldc + col) = __floats2half2_rn(v[2], v[3]);
            }
        }
    }
}

// ---------------- fp16 tensor-core causal flash attention -------------------
// QKV fused layout: [B*S, 3*DIM]; q at col h*64, k at DIM+h*64, v at 2*DIM+h*64.
// 64x64 tiles, 4 warps (warp = 16 q-rows), m16n8k16 MMA, online softmax on frags.
#define LDHA 72
#define LDQKV (3 * DIM)

__global__ __launch_bounds__(128)
void attn_fp16(const __half* __restrict__ QKV, __half* __restrict__ O) {
    __shared__ __half Qs[64 * LDHA];
    __shared__ __half Ks[64 * LDHA];
    __shared__ __half Vs[64 * LDHA];

    int qb = blockIdx.x, h = blockIdx.y, b = blockIdx.z;
    int tid = threadIdx.x, lane = tid & 31, wid = tid >> 5;
    const float SC = 0.125f * 1.44269504089f;   // 1/sqrt(64) * log2(e)

    const __half* Qg = QKV + (size_t)b * SEQ * LDQKV + h * HDIM;
    const __half* Kg = Qg + DIM;
    const __half* Vg = Qg + 2 * DIM;

    // Q tile fill (group 0)
    #pragma unroll
    for (int i = 0; i < 4; i++) {
        int id = tid + i * 128;
        int row = id >> 3, ch = id & 7;
        cp16(smem_u32(Qs) + row * (LDHA * 2) + ch * 16,
             Qg + (size_t)(qb * 64 + row) * LDQKV + ch * 8);
    }
    cp_commit();

    float o[8][4];
    #pragma unroll
    for (int j = 0; j < 8; j++)
        #pragma unroll
        for (int e = 0; e < 4; e++) o[j][e] = 0.0f;
    float m0 = -CUDART_INF_F, m1 = -CUDART_INF_F, l0 = 0.0f, l1 = 0.0f;

    unsigned lrow = (unsigned)(lane & 15);
    unsigned lcolb = (unsigned)((lane >> 4) * 16);
    unsigned qaddr = smem_u32(Qs) + (wid * 16 + lrow) * (LDHA * 2) + lcolb;
    unsigned kbase = smem_u32(Ks) + lrow * (LDHA * 2) + lcolb;
    unsigned vbase = smem_u32(Vs) + lrow * (LDHA * 2) + lcolb;

    for (int kb = 0; kb <= qb; kb++) {
        __syncthreads();    // previous tile fully consumed
        #pragma unroll
        for (int i = 0; i < 4; i++) {
            int id = tid + i * 128;
            int row = id >> 3, ch = id & 7;
            cp16(smem_u32(Ks) + row * (LDHA * 2) + ch * 16,
                 Kg + (size_t)(kb * 64 + row) * LDQKV + ch * 8);
        }
        #pragma unroll
        for (int i = 0; i < 4; i++) {
            int id = tid + i * 128;
            int row = id >> 3, ch = id & 7;
            cp16(smem_u32(Vs) + row * (LDHA * 2) + ch * 16,
                 Vg + (size_t)(kb * 64 + row) * LDQKV + ch * 8);
        }
        cp_commit();
        cp_wait<0>();
        __syncthreads();

        // ---- S = Q K^T (fp32 acc) ----
        float s[8][4];
        #pragma unroll
        for (int j = 0; j < 8; j++)
            #pragma unroll
            for (int e = 0; e < 4; e++) s[j][e] = 0.0f;
        #pragma unroll
        for (int kk = 0; kk < 4; kk++) {
            uint32_t aq0, aq1, aq2, aq3;
            LDMX4(aq0, aq1, aq2, aq3, qaddr + kk * 32);
            #pragma unroll
            for (int nb = 0; nb < 4; nb++) {
                uint32_t b0, b1, b2, b3;
                LDMX4(b0, b1, b2, b3, kbase + (unsigned)(nb * 16 * LDHA * 2) + kk * 32);
                MMA16816(s[nb * 2],     aq0, aq1, aq2, aq3, b0, b2);
                MMA16816(s[nb * 2 + 1], aq0, aq1, aq2, aq3, b1, b3);
            }
        }

        // ---- scale (+causal mask) in log2 domain ----
        int r0 = wid * 16 + (lane >> 2);
        int c0 = (lane & 3) * 2;
        if (kb == qb) {
            #pragma unroll
            for (int j = 0; j < 8; j++) {
                int col = j * 8 + c0;
                #pragma unroll
                for (int e = 0; e < 4; e++) {
                    int row = r0 + (e >> 1) * 8;
                    int cc  = col + (e & 1);
                    s[j][e] = (cc > row) ? -CUDART_INF_F : s[j][e] * SC;
                }
            }
        } else {
            #pragma unroll
            for (int j = 0; j < 8; j++)
                #pragma unroll
                for (int e = 0; e < 4; e++) s[j][e] *= SC;
        }

        // ---- online softmax (rows r0, r0+8) ----
        float rm0 = -CUDART_INF_F, rm1 = -CUDART_INF_F;
        #pragma unroll
        for (int j = 0; j < 8; j++) {
            rm0 = fmaxf(rm0, fmaxf(s[j][0], s[j][1]));
            rm1 = fmaxf(rm1, fmaxf(s[j][2], s[j][3]));
        }
        rm0 = fmaxf(rm0, __shfl_xor_sync(0xFFFFFFFFu, rm0, 1));
        rm0 = fmaxf(rm0, __shfl_xor_sync(0xFFFFFFFFu, rm0, 2));
        rm1 = fmaxf(rm1, __shfl_xor_sync(0xFFFFFFFFu, rm1, 1));
        rm1 = fmaxf(rm1, __shfl_xor_sync(0xFFFFFFFFu, rm1, 2));
        float mn0 = fmaxf(m0, rm0), mn1 = fmaxf(m1, rm1);
        float a0 = ex2f(m0 - mn0), a1 = ex2f(m1 - mn1);
        m0 = mn0; m1 = mn1;
        float rs0 = 0.0f, rs1 = 0.0f;
        #pragma unroll
        for (int j = 0; j < 8; j++) {
            s[j][0] = ex2f(s[j][0] - mn0); rs0 += s[j][0];
            s[j][1] = ex2f(s[j][1] - mn0); rs0 += s[j][1];
            s[j][2] = ex2f(s[j][2] - mn1); rs1 += s[j][2];
            s[j][3] = ex2f(s[j][3] - mn1); rs1 += s[j][3];
        }
        rs0 += __shfl_xor_sync(0xFFFFFFFFu, rs0, 1);
        rs0 += __shfl_xor_sync(0xFFFFFFFFu, rs0, 2);
        rs1 += __shfl_xor_sync(0xFFFFFFFFu, rs1, 1);
        rs1 += __shfl_xor_sync(0xFFFFFFFFu, rs1, 2);
        l0 = l0 * a0 + rs0;
        l1 = l1 * a1 + rs1;

        // ---- rescale O, then O += P V ----
        #pragma unroll
        for (int j = 0; j < 8; j++) {
            o[j][0] *= a0; o[j][1] *= a0; o[j][2] *= a1; o[j][3] *= a1;
        }
        #pragma unroll
        for (int kk = 0; kk < 4; kk++) {
            uint32_t p0 = packh2(s[2 * kk][0],     s[2 * kk][1]);
            uint32_t p1 = packh2(s[2 * kk][2],     s[2 * kk][3]);
            uint32_t p2 = packh2(s[2 * kk + 1][0], s[2 * kk + 1][1]);
            uint32_t p3 = packh2(s[2 * kk + 1][2], s[2 * kk + 1][3]);
            #pragma unroll
            for (int nb2 = 0; nb2 < 4; nb2++) {
                uint32_t v0, v1, v2, v3;
                LDMX4T(v0, v1, v2, v3,
                       vbase + (unsigned)(kk * 16 * LDHA * 2) + nb2 * 32);
                MMA16816(o[nb2 * 2],     p0, p1, p2, p3, v0, v1);
                MMA16816(o[nb2 * 2 + 1], p0, p1, p2, p3, v2, v3);
            }
        }
    }

    // ---- normalize + write fp16 ----
    float inv0 = 1.0f / l0, inv1 = 1.0f / l1;
    int row_g = qb * 64 + wid * 16 + (lane >> 2);
    size_t ob = (size_t)(b * SEQ + row_g) * DIM + h * HDIM + (lane & 3) * 2;
    #pragma unroll
    for (int j = 0; j < 8; j++) {
        *reinterpret_cast<__half2*>(O + ob + j * 8) =
            __floats2half2_rn(o[j][0] * inv0, o[j][1] * inv0);
        *reinterpret_cast<__half2*>(O + ob + 8 * DIM + j * 8) =
            __floats2half2_rn(o[j][2] * inv1, o[j][3] * inv1);
    }
}

// ---------------- weight fp32 -> fp16 (RNE) ----------------
__global__ void cvt_fp16_kernel(const float* __restrict__ in, __half* __restrict__ out, int n4) {
    int i = blockIdx.x * blockDim.x + threadIdx.x;
    if (i >= n4) return;
    float4 v = reinterpret_cast<const float4*>(in)[i];
    reinterpret_cast<__half2*>(out)[i * 2]     = __floats2half2_rn(v.x, v.y);
    reinterpret_cast<__half2*>(out)[i * 2 + 1] = __floats2half2_rn(v.z, v.w);
}

// ---------------- RMSNorm: one block per token, fp16 out ----------------
__global__ void rmsnorm_kernel(const float* __restrict__ x,
                               const float* __restrict__ w,
                               __half* __restrict__ out) {
    int t = blockIdx.x;
    int tid = threadIdx.x;
    const float4* xr = reinterpret_cast<const float4*>(x + (size_t)t * DIM);
    float4 v = xr[tid];
    float ss = v.x * v.x + v.y * v.y + v.z * v.z + v.w * v.w;
    #pragma unroll
    for (int o = 16; o > 0; o >>= 1) ss += __shfl_xor_sync(0xFFFFFFFFu, ss, o);
    __shared__ float red[8];
    if ((tid & 31) == 0) red[tid >> 5] = ss;
    __syncthreads();
    if (tid < 8) {
        float s = red[tid];
        #pragma unroll
        for (int o = 4; o > 0; o >>= 1) s += __shfl_xor_sync(0xFFu, s, o);
        if (tid == 0) red[0] = s;
    }
    __syncthreads();
    float scale = rsqrtf(red[0] * (1.0f / DIM) + EPS);
    float4 wv = reinterpret_cast<const float4*>(w)[tid];
    __half2* op = reinterpret_cast<__half2*>(out + (size_t)t * DIM) + tid * 2;
    op[0] = __floats2half2_rn(v.x * scale * wv.x, v.y * scale * wv.y);
    op[1] = __floats2half2_rn(v.z * scale * wv.z, v.w * scale * wv.w);
}

// ---------------- SiLU(gate) * up -> fp16 act (fused gu layout) -------------
__global__ void silu_mul_kernel(const float* __restrict__ gu, __half* __restrict__ act, int n4) {
    int i = blockIdx.x * blockDim.x + threadIdx.x;
    if (i >= n4) return;
    int row = i >> 10;            // HIDDEN/4 = 1024 float4 per row
    int c   = i & 1023;
    const float4* gp = reinterpret_cast<const float4*>(gu) + (size_t)row * 2048 + c;
    float4 g = gp[0];
    float4 u = gp[1024];
    float rx = g.x / (1.0f + __expf(-g.x)) * u.x;
    float ry = g.y / (1.0f + __expf(-g.y)) * u.y;
    float rz = g.z / (1.0f + __expf(-g.z)) * u.z;
    float rw = g.w / (1.0f + __expf(-g.w)) * u.w;
    __half2* ap = reinterpret_cast<__half2*>(act) + (size_t)i * 2;
    ap[0] = __floats2half2_rn(rx, ry);
    ap[1] = __floats2half2_rn(rz, rw);
}

// ---------------- launch ----------------
extern "C" void kernel_launch(void* const* d_in, const int* in_sizes, int n_in,
                              void* d_out, int out_size) {
    const float* x     = (const float*)d_in[0];
    const float* wq    = (const float*)d_in[1];
    const float* wk    = (const float*)d_in[2];
    const float* wv    = (const float*)d_in[3];
    const float* wo    = (const float*)d_in[4];
    const float* wgate = (const float*)d_in[5];
    const float* wup   = (const float*)d_in[6];
    const float* wdown = (const float*)d_in[7];
    const float* n1w   = (const float*)d_in[8];
    const float* n2w   = (const float*)d_in[9];
    float* out = (float*)d_out;

    __half *h, *qkv, *att, *h2, *act, *cwqkv, *cwo, *cwgu, *cwd;
    float *x2, *gu;
    cudaGetSymbolAddress((void**)&h,     g_h);
    cudaGetSymbolAddress((void**)&qkv,   g_qkv);
    cudaGetSymbolAddress((void**)&att,   g_att);
    cudaGetSymbolAddress((void**)&x2,    g_x2);
    cudaGetSymbolAddress((void**)&h2,    g_h2);
    cudaGetSymbolAddress((void**)&gu,    g_gu);
    cudaGetSymbolAddress((void**)&act,   g_act);
    cudaGetSymbolAddress((void**)&cwqkv, g_wqkv);
    cudaGetSymbolAddress((void**)&cwo,   g_wo);
    cudaGetSymbolAddress((void**)&cwgu,  g_wgu);
    cudaGetSymbolAddress((void**)&cwd,   g_wd);

    // weight conversion into fused layouts
    int nw1 = DIM * DIM / 4, nw2 = HIDDEN * DIM / 4;
    cvt_fp16_kernel<<<(nw1 + 255) / 256, 256>>>(wq,    cwqkv,               nw1);
    cvt_fp16_kernel<<<(nw1 + 255) / 256, 256>>>(wk,    cwqkv + DIM * DIM,   nw1);
    cvt_fp16_kernel<<<(nw1 + 255) / 256, 256>>>(wv,    cwqkv + 2 * DIM * DIM, nw1);
    cvt_fp16_kernel<<<(nw1 + 255) / 256, 256>>>(wo,    cwo,                 nw1);
    cvt_fp16_kernel<<<(nw2 + 255) / 256, 256>>>(wgate, cwgu,                nw2);
    cvt_fp16_kernel<<<(nw2 + 255) / 256, 256>>>(wup,   cwgu + HIDDEN * DIM, nw2);
    cvt_fp16_kernel<<<(nw2 + 255) / 256, 256>>>(wdown, cwd,                 nw2);

    rmsnorm_kernel<<<NTOK, 256>>>(x, n1w, h);

    // fused QKV: [NTOK, 3072] fp16
    dim3 gq(3 * DIM / 128, NTOK / 128);
    gemm_fp16<__half><<<gq, 256>>>(h, cwqkv, nullptr, qkv, DIM, 3 * DIM);

    dim3 ga(SEQ / 64, NHEADS, BATCH);
    attn_fp16<<<ga, 128>>>(qkv, att);

    dim3 g1(DIM / 128, NTOK / 128);
    gemm_fp16<float><<<g1, 256>>>(att, cwo, x, x2, DIM, DIM);

    rmsnorm_kernel<<<NTOK, 256>>>(x2, n2w, h2);

    // fused gate|up: [NTOK, 8192] fp32
    dim3 g2(2 * HIDDEN / 128, NTOK / 128);
    gemm_fp16<float><<<g2, 256>>>(h2, cwgu, nullptr, gu, DIM, 2 * HIDDEN);

    int n4 = NTOK * HIDDEN / 4;
    silu_mul_kernel<<<(n4 + 255) / 256, 256>>>(gu, act, n4);

    gemm_fp16<float><<<g1, 256>>>(act, cwd, x2, out, HIDDEN, DIM);
}

// round 7
// speedup vs baseline: 6.4721x; 1.0344x over previous
#include <cuda_runtime.h>
#include <cuda_fp16.h>
#include <math.h>
#include <math_constants.h>
#include <stdint.h>

#define DIM     1024
#define NHEADS  16
#define HDIM    64
#define HIDDEN  4096
#define BATCH   2
#define SEQ     2048
#define NTOK    (BATCH * SEQ)
#define EPS     1e-5f

// ---------------- scratch (static device globals; no allocs) ----------------
__device__ __half g_h   [NTOK * DIM];         // rmsnorm1 out
__device__ __half g_qkv [NTOK * 3 * DIM];     // fused qkv out (fp16)
__device__ __half g_att [NTOK * DIM];         // attention out
__device__ float  g_x2  [NTOK * DIM];         // residual after attention
__device__ __half g_h2  [NTOK * DIM];         // rmsnorm2 out
__device__ __half g_act [NTOK * HIDDEN];      // silu(gate)*up (fp16)
// fp16 weights: wqkv = [wq;wk;wv] rows; wgu rows interleaved gate/up
__device__ __half g_wqkv[3 * DIM * DIM];
__device__ __half g_wo  [DIM * DIM];
__device__ __half g_wgu [2 * HIDDEN * DIM];
__device__ __half g_wd  [DIM * HIDDEN];

// ---------------- helpers ----------------
__device__ __forceinline__ void cp16(unsigned dst, const void* src) {
    asm volatile("cp.async.cg.shared.global [%0], [%1], 16;\n" :: "r"(dst), "l"(src));
}
__device__ __forceinline__ void cp_commit() {
    asm volatile("cp.async.commit_group;\n");
}
template <int N>
__device__ __forceinline__ void cp_wait() {
    asm volatile("cp.async.wait_group %0;\n" :: "n"(N));
}
__device__ __forceinline__ unsigned smem_u32(const void* p) {
    return (unsigned)__cvta_generic_to_shared(p);
}
__device__ __forceinline__ float ex2f(float x) {
    float r; asm("ex2.approx.f32 %0, %1;" : "=f"(r) : "f"(x)); return r;
}
__device__ __forceinline__ uint32_t packh2(float a, float b) {
    __half2 h = __floats2half2_rn(a, b);
    return *reinterpret_cast<uint32_t*>(&h);
}
#define LDMX4(r0, r1, r2, r3, addr) \
    asm volatile("ldmatrix.sync.aligned.m8n8.x4.shared.b16 {%0,%1,%2,%3}, [%4];" \
                 : "=r"(r0), "=r"(r1), "=r"(r2), "=r"(r3) : "r"(addr))
#define LDMX4T(r0, r1, r2, r3, addr) \
    asm volatile("ldmatrix.sync.aligned.m8n8.x4.trans.shared.b16 {%0,%1,%2,%3}, [%4];" \
                 : "=r"(r0), "=r"(r1), "=r"(r2), "=r"(r3) : "r"(addr))
#define MMA16816(c, a0, a1, a2, a3, b0, b1) \
    asm volatile("mma.sync.aligned.m16n8k16.row.col.f32.f16.f16.f32 " \
                 "{%0,%1,%2,%3}, {%4,%5,%6,%7}, {%8,%9}, {%0,%1,%2,%3};" \
                 : "+f"((c)[0]), "+f"((c)[1]), "+f"((c)[2]), "+f"((c)[3]) \
                 : "r"(a0), "r"(a1), "r"(a2), "r"(a3), "r"(b0), "r"(b1))

// ---------------- fp16 tensor-core GEMM core (NT, 3-stage pipeline) ---------
// A: [M,K] fp16 row-major, B: [N,K] fp16 row-major.
// 128x128 tile, BK=32, 8 warps (2x4), warp tile 64x32.
#define LDH        40
#define TILE_BYTES (128 * LDH * 2)          // 10240
#define STG_BYTES  (2 * TILE_BYTES)         // A+B per stage
#define GEMM_DSM   (3 * STG_BYTES)          // 61440

__device__ __forceinline__ void fill_stage_h(unsigned stgbase,
                                             const __half* A, const __half* B,
                                             int K, int m0, int n0, int kt, int tid) {
    int row = tid >> 2;
    int kc  = tid & 3;
    const __half* ag = A + (size_t)(m0 + row) * K + kt * 32 + kc * 8;
    const __half* bg = B + (size_t)(n0 + row) * K + kt * 32 + kc * 8;
    unsigned off  = (unsigned)(row * LDH * 2 + kc * 16);
    unsigned off2 = off + 64 * LDH * 2;
    size_t gstep = (size_t)64 * K;
    cp16(stgbase + off,  ag);
    cp16(stgbase + off2, ag + gstep);
    cp16(stgbase + TILE_BYTES + off,  bg);
    cp16(stgbase + TILE_BYTES + off2, bg + gstep);
    cp_commit();
}

// mainloop producing acc; returns nothing, acc by ref
__device__ __forceinline__ void gemm_mainloop(float acc[4][4][4],
                                              const __half* A, const __half* B,
                                              int K, int m0, int n0,
                                              int tid, int lane, int wid,
                                              int wm, int wn, unsigned base) {
    #pragma unroll
    for (int i = 0; i < 4; i++)
        #pragma unroll
        for (int j = 0; j < 4; j++)
            #pragma unroll
            for (int c = 0; c < 4; c++) acc[i][j][c] = 0.0f;

    const int NT = K >> 5;
    fill_stage_h(base,             A, B, K, m0, n0, 0, tid);
    fill_stage_h(base + STG_BYTES, A, B, K, m0, n0, 1, tid);

    unsigned lrow = (unsigned)(lane & 15);
    unsigned lcolb = (unsigned)((lane >> 4) * 16);

    int st = 0;
    for (int it = 0; it < NT; it++) {
        cp_wait<1>();
        __syncthreads();

        if (it + 2 < NT) {
            int fs = st + 2; if (fs >= 3) fs -= 3;
            fill_stage_h(base + fs * STG_BYTES, A, B, K, m0, n0, it + 2, tid);
        } else {
            cp_commit();
        }

        unsigned bA = base + st * STG_BYTES;
        unsigned bB = bA + TILE_BYTES;
        #pragma unroll
        for (int ks = 0; ks < 2; ks++) {
            unsigned kbyte = (unsigned)(ks * 32) + lcolb;
            uint32_t af[4][4], bf[2][4];
            #pragma unroll
            for (int mi = 0; mi < 4; mi++) {
                unsigned addr = bA + (unsigned)((wm + mi * 16 + lrow) * LDH * 2) + kbyte;
                LDMX4(af[mi][0], af[mi][1], af[mi][2], af[mi][3], addr);
            }
            #pragma unroll
            for (int nb = 0; nb < 2; nb++) {
                unsigned addr = bB + (unsigned)((wn + nb * 16 + lrow) * LDH * 2) + kbyte;
                LDMX4(bf[nb][0], bf[nb][1], bf[nb][2], bf[nb][3], addr);
            }
            #pragma unroll
            for (int mi = 0; mi < 4; mi++) {
                #pragma unroll
                for (int ni = 0; ni < 4; ni++) {
                    int nb = ni >> 1, blk = ni & 1;
                    MMA16816(acc[mi][ni], af[mi][0], af[mi][1], af[mi][2], af[mi][3],
                             bf[nb][blk], bf[nb][blk + 2]);
                }
            }
        }
        st++; if (st == 3) st = 0;
    }
}

template<typename OT>
__global__ __launch_bounds__(256)
void gemm_fp16(const __half* __restrict__ A, const __half* __restrict__ B,
               const float* __restrict__ res, OT* __restrict__ C,
               int K, int ldc) {
    extern __shared__ __half dyn[];
    unsigned base = smem_u32(dyn);
    int tid = threadIdx.x, lane = tid & 31, wid = tid >> 5;
    int wm = (wid & 1) * 64, wn = (wid >> 1) * 32;
    int m0 = blockIdx.y * 128, n0 = blockIdx.x * 128;

    float acc[4][4][4];
    gemm_mainloop(acc, A, B, K, m0, n0, tid, lane, wid, wm, wn, base);

    int gr = lane >> 2;
    int gc = (lane & 3) * 2;
    #pragma unroll
    for (int mi = 0; mi < 4; mi++) {
        #pragma unroll
        for (int ni = 0; ni < 4; ni++) {
            size_t row = (size_t)(m0 + wm + mi * 16 + gr);
            size_t col = (size_t)(n0 + wn + ni * 8 + gc);
            float v[4] = { acc[mi][ni][0], acc[mi][ni][1], acc[mi][ni][2], acc[mi][ni][3] };
            if (res) {
                float2 r0 = *reinterpret_cast<const float2*>(res + row * ldc + col);
                float2 r1 = *reinterpret_cast<const float2*>(res + (row + 8) * ldc + col);
                v[0] += r0.x; v[1] += r0.y; v[2] += r1.x; v[3] += r1.y;
            }
            if (sizeof(OT) == 4) {
                float* Cf = (float*)C;
                *reinterpret_cast<float2*>(Cf + row * ldc + col) = make_float2(v[0], v[1]);
                *reinterpret_cast<float2*>(Cf + (row + 8) * ldc + col) = make_float2(v[2], v[3]);
            } else {
                __half* Ch = (__half*)C;
                *reinterpret_cast<__half2*>(Ch + row * ldc + col) = __floats2half2_rn(v[0], v[1]);
                *reinterpret_cast<__half2*>(Ch + (row + 8) * ldc + col) = __floats2half2_rn(v[2], v[3]);
            }
        }
    }
}

// gate/up GEMM with fused SiLU epilogue. B rows interleaved (2j=gate_j, 2j+1=up_j).
// N spans 8192 interleaved cols; act gets silu(gate)*up at col/2.
__global__ __launch_bounds__(256)
void gemm_gu(const __half* __restrict__ A, const __half* __restrict__ B,
             __half* __restrict__ act, int K) {
    extern __shared__ __half dyn[];
    unsigned base = smem_u32(dyn);
    int tid = threadIdx.x, lane = tid & 31, wid = tid >> 5;
    int wm = (wid & 1) * 64, wn = (wid >> 1) * 32;
    int m0 = blockIdx.y * 128, n0 = blockIdx.x * 128;

    float acc[4][4][4];
    gemm_mainloop(acc, A, B, K, m0, n0, tid, lane, wid, wm, wn, base);

    int gr = lane >> 2;
    int gc = (lane & 3) * 2;
    #pragma unroll
    for (int mi = 0; mi < 4; mi++) {
        #pragma unroll
        for (int ni = 0; ni < 4; ni++) {
            size_t row = (size_t)(m0 + wm + mi * 16 + gr);
            int col = n0 + wn + ni * 8 + gc;          // even: gate, odd: up
            float g0 = acc[mi][ni][0], u0 = acc[mi][ni][1];
            float g1 = acc[mi][ni][2], u1 = acc[mi][ni][3];
            float r0 = g0 / (1.0f + __expf(-g0)) * u0;
            float r1 = g1 / (1.0f + __expf(-g1)) * u1;
            act[row * HIDDEN + (col >> 1)]       = __float2half_rn(r0);
            act[(row + 8) * HIDDEN + (col >> 1)] = __float2half_rn(r1);
        }
    }
}

// ---------------- fp16 tensor-core causal flash attention -------------------
// QKV fused layout: [B*S, 3*DIM]; q at col h*64, k at DIM+h*64, v at 2*DIM+h*64.
// 64x64 tiles, 4 warps, m16n8k16, online softmax on frags, 2-stage K/V buffer.
#define LDHA 72
#define LDQKV (3 * DIM)

__global__ __launch_bounds__(128)
void attn_fp16(const __half* __restrict__ QKV, __half* __restrict__ O) {
    __shared__ __half Qs[64 * LDHA];
    __shared__ __half Ks[2][64 * LDHA];
    __shared__ __half Vs[2][64 * LDHA];

    int qb = blockIdx.x, h = blockIdx.y, b = blockIdx.z;
    int tid = threadIdx.x, lane = tid & 31, wid = tid >> 5;
    const float SC = 0.125f * 1.44269504089f;

    const __half* Qg = QKV + (size_t)b * SEQ * LDQKV + h * HDIM;
    const __half* Kg = Qg + DIM;
    const __half* Vg = Qg + 2 * DIM;

    // prologue: Q + KV stage 0 (group 0)
    #pragma unroll
    for (int i = 0; i < 4; i++) {
        int id = tid + i * 128;
        int row = id >> 3, ch = id & 7;
        cp16(smem_u32(Qs) + row * (LDHA * 2) + ch * 16,
             Qg + (size_t)(qb * 64 + row) * LDQKV + ch * 8);
    }
    #pragma unroll
    for (int i = 0; i < 4; i++) {
        int id = tid + i * 128;
        int row = id >> 3, ch = id & 7;
        unsigned so = (unsigned)(row * (LDHA * 2) + ch * 16);
        size_t go = (size_t)row * LDQKV + ch * 8;
        cp16(smem_u32(Ks[0]) + so, Kg + go);
        cp16(smem_u32(Vs[0]) + so, Vg + go);
    }
    cp_commit();

    float o[8][4];
    #pragma unroll
    for (int j = 0; j < 8; j++)
        #pragma unroll
        for (int e = 0; e < 4; e++) o[j][e] = 0.0f;
    float m0 = -CUDART_INF_F, m1 = -CUDART_INF_F, l0 = 0.0f, l1 = 0.0f;

    unsigned lrow = (unsigned)(lane & 15);
    unsigned lcolb = (unsigned)((lane >> 4) * 16);
    unsigned qaddr = smem_u32(Qs) + (wid * 16 + lrow) * (LDHA * 2) + lcolb;

    for (int kb = 0; kb <= qb; kb++) {
        if (kb) __syncthreads();    // stage (kb+1)&1 fully consumed by compute kb-1

        if (kb < qb) {              // prefetch KV stage kb+1
            int s = (kb + 1) & 1;
            #pragma unroll
            for (int i = 0; i < 4; i++) {
                int id = tid + i * 128;
                int row = id >> 3, ch = id & 7;
                unsigned so = (unsigned)(row * (LDHA * 2) + ch * 16);
                size_t go = (size_t)((kb + 1) * 64 + row) * LDQKV + ch * 8;
                cp16(smem_u32(Ks[s]) + so, Kg + go);
                cp16(smem_u32(Vs[s]) + so, Vg + go);
            }
        }
        cp_commit();
        cp_wait<1>();
        __syncthreads();

        int st = kb & 1;
        unsigned kbase = smem_u32(Ks[st]) + lrow * (LDHA * 2) + lcolb;
        unsigned vbase = smem_u32(Vs[st]) + lrow * (LDHA * 2) + lcolb;

        // ---- S = Q K^T ----
        float s[8][4];
        #pragma unroll
        for (int j = 0; j < 8; j++)
            #pragma unroll
            for (int e = 0; e < 4; e++) s[j][e] = 0.0f;
        #pragma unroll
        for (int kk = 0; kk < 4; kk++) {
            uint32_t aq0, aq1, aq2, aq3;
            LDMX4(aq0, aq1, aq2, aq3, qaddr + kk * 32);
            #pragma unroll
            for (int nb = 0; nb < 4; nb++) {
                uint32_t b0, b1, b2, b3;
                LDMX4(b0, b1, b2, b3, kbase + (unsigned)(nb * 16 * LDHA * 2) + kk * 32);
                MMA16816(s[nb * 2],     aq0, aq1, aq2, aq3, b0, b2);
                MMA16816(s[nb * 2 + 1], aq0, aq1, aq2, aq3, b1, b3);
            }
        }

        // ---- scale (+causal mask), log2 domain ----
        int r0 = wid * 16 + (lane >> 2);
        int c0 = (lane & 3) * 2;
        if (kb == qb) {
            #pragma unroll
            for (int j = 0; j < 8; j++) {
                int col = j * 8 + c0;
                #pragma unroll
                for (int e = 0; e < 4; e++) {
                    int row = r0 + (e >> 1) * 8;
                    int cc  = col + (e & 1);
                    s[j][e] = (cc > row) ? -CUDART_INF_F : s[j][e] * SC;
                }
            }
        } else {
            #pragma unroll
            for (int j = 0; j < 8; j++)
                #pragma unroll
                for (int e = 0; e < 4; e++) s[j][e] *= SC;
        }

        // ---- online softmax ----
        float rm0 = -CUDART_INF_F, rm1 = -CUDART_INF_F;
        #pragma unroll
        for (int j = 0; j < 8; j++) {
            rm0 = fmaxf(rm0, fmaxf(s[j][0], s[j][1]));
            rm1 = fmaxf(rm1, fmaxf(s[j][2], s[j][3]));
        }
        rm0 = fmaxf(rm0, __shfl_xor_sync(0xFFFFFFFFu, rm0, 1));
        rm0 = fmaxf(rm0, __shfl_xor_sync(0xFFFFFFFFu, rm0, 2));
        rm1 = fmaxf(rm1, __shfl_xor_sync(0xFFFFFFFFu, rm1, 1));
        rm1 = fmaxf(rm1, __shfl_xor_sync(0xFFFFFFFFu, rm1, 2));
        float mn0 = fmaxf(m0, rm0), mn1 = fmaxf(m1, rm1);
        float a0 = ex2f(m0 - mn0), a1 = ex2f(m1 - mn1);
        m0 = mn0; m1 = mn1;
        float rs0 = 0.0f, rs1 = 0.0f;
        #pragma unroll
        for (int j = 0; j < 8; j++) {
            s[j][0] = ex2f(s[j][0] - mn0); rs0 += s[j][0];
            s[j][1] = ex2f(s[j][1] - mn0); rs0 += s[j][1];
            s[j][2] = ex2f(s[j][2] - mn1); rs1 += s[j][2];
            s[j][3] = ex2f(s[j][3] - mn1); rs1 += s[j][3];
        }
        rs0 += __shfl_xor_sync(0xFFFFFFFFu, rs0, 1);
        rs0 += __shfl_xor_sync(0xFFFFFFFFu, rs0, 2);
        rs1 += __shfl_xor_sync(0xFFFFFFFFu, rs1, 1);
        rs1 += __shfl_xor_sync(0xFFFFFFFFu, rs1, 2);
        l0 = l0 * a0 + rs0;
        l1 = l1 * a1 + rs1;

        // ---- O = O*alpha + P V ----
        #pragma unroll
        for (int j = 0; j < 8; j++) {
            o[j][0] *= a0; o[j][1] *= a0; o[j][2] *= a1; o[j][3] *= a1;
        }
        #pragma unroll
        for (int kk = 0; kk < 4; kk++) {
            uint32_t p0 = packh2(s[2 * kk][0],     s[2 * kk][1]);
            uint32_t p1 = packh2(s[2 * kk][2],     s[2 * kk][3]);
            uint32_t p2 = packh2(s[2 * kk + 1][0], s[2 * kk + 1][1]);
            uint32_t p3 = packh2(s[2 * kk + 1][2], s[2 * kk + 1][3]);
            #pragma unroll
            for (int nb2 = 0; nb2 < 4; nb2++) {
                uint32_t v0, v1, v2, v3;
                LDMX4T(v0, v1, v2, v3,
                       vbase + (unsigned)(kk * 16 * LDHA * 2) + nb2 * 32);
                MMA16816(o[nb2 * 2],     p0, p1, p2, p3, v0, v1);
                MMA16816(o[nb2 * 2 + 1], p0, p1, p2, p3, v2, v3);
            }
        }
    }

    float inv0 = 1.0f / l0, inv1 = 1.0f / l1;
    int row_g = qb * 64 + wid * 16 + (lane >> 2);
    size_t ob = (size_t)(b * SEQ + row_g) * DIM + h * HDIM + (lane & 3) * 2;
    #pragma unroll
    for (int j = 0; j < 8; j++) {
        *reinterpret_cast<__half2*>(O + ob + j * 8) =
            __floats2half2_rn(o[j][0] * inv0, o[j][1] * inv0);
        *reinterpret_cast<__half2*>(O + ob + 8 * DIM + j * 8) =
            __floats2half2_rn(o[j][2] * inv1, o[j][3] * inv1);
    }
}

// ---------------- weight conversions (fp32 -> fp16 RNE, fused layouts) ------
__global__ void cvt_qkv_kernel(const float* __restrict__ wq, const float* __restrict__ wk,
                               const float* __restrict__ wv, __half* __restrict__ dst, int nw1) {
    int i = blockIdx.x * blockDim.x + threadIdx.x;
    if (i >= 3 * nw1) return;
    const float* src = (i < nw1) ? (wq + (size_t)i * 4)
                     : (i < 2 * nw1) ? (wk + (size_t)(i - nw1) * 4)
                     : (wv + (size_t)(i - 2 * nw1) * 4);
    float4 v = *reinterpret_cast<const float4*>(src);
    reinterpret_cast<__half2*>(dst)[i * 2]     = __floats2half2_rn(v.x, v.y);
    reinterpret_cast<__half2*>(dst)[i * 2 + 1] = __floats2half2_rn(v.z, v.w);
}

// interleave: dst row 2j = wgate row j, dst row 2j+1 = wup row j (rows of DIM)
__global__ void cvt_gu_kernel(const float* __restrict__ wgate, const float* __restrict__ wup,
                              __half* __restrict__ dst, int nw2) {
    int i = blockIdx.x * blockDim.x + threadIdx.x;   // float4 idx in dst
    if (i >= 2 * nw2) return;
    int r = i >> 8;            // DIM/4 = 256 float4 per row
    int c = i & 255;
    const float* srcb = (r & 1) ? wup : wgate;
    float4 v = *reinterpret_cast<const float4*>(srcb + (size_t)(r >> 1) * DIM + c * 4);
    reinterpret_cast<__half2*>(dst)[i * 2]     = __floats2half2_rn(v.x, v.y);
    reinterpret_cast<__half2*>(dst)[i * 2 + 1] = __floats2half2_rn(v.z, v.w);
}

__global__ void cvt_fp16_kernel(const float* __restrict__ in, __half* __restrict__ out, int n4) {
    int i = blockIdx.x * blockDim.x + threadIdx.x;
    if (i >= n4) return;
    float4 v = reinterpret_cast<const float4*>(in)[i];
    reinterpret_cast<__half2*>(out)[i * 2]     = __floats2half2_rn(v.x, v.y);
    reinterpret_cast<__half2*>(out)[i * 2 + 1] = __floats2half2_rn(v.z, v.w);
}

// ---------------- RMSNorm: one block per token, fp16 out ----------------
__global__ void rmsnorm_kernel(const float* __restrict__ x,
                               const float* __restrict__ w,
                               __half* __restrict__ out) {
    int t = blockIdx.x;
    int tid = threadIdx.x;
    const float4* xr = reinterpret_cast<const float4*>(x + (size_t)t * DIM);
    float4 v = xr[tid];
    float ss = v.x * v.x + v.y * v.y + v.z * v.z + v.w * v.w;
    #pragma unroll
    for (int o = 16; o > 0; o >>= 1) ss += __shfl_xor_sync(0xFFFFFFFFu, ss, o);
    __shared__ float red[8];
    if ((tid & 31) == 0) red[tid >> 5] = ss;
    __syncthreads();
    if (tid < 8) {
        float s = red[tid];
        #pragma unroll
        for (int o = 4; o > 0; o >>= 1) s += __shfl_xor_sync(0xFFu, s, o);
        if (tid == 0) red[0] = s;
    }
    __syncthreads();
    float scale = rsqrtf(red[0] * (1.0f / DIM) + EPS);
    float4 wv = reinterpret_cast<const float4*>(w)[tid];
    __half2* op = reinterpret_cast<__half2*>(out + (size_t)t * DIM) + tid * 2;
    op[0] = __floats2half2_rn(v.x * scale * wv.x, v.y * scale * wv.y);
    op[1] = __floats2half2_rn(v.z * scale * wv.z, v.w * scale * wv.w);
}

// ---------------- launch ----------------
extern "C" void kernel_launch(void* const* d_in, const int* in_sizes, int n_in,
                              void* d_out, int out_size) {
    const float* x     = (const float*)d_in[0];
    const float* wq    = (const float*)d_in[1];
    const float* wk    = (const float*)d_in[2];
    const float* wv    = (const float*)d_in[3];
    const float* wo    = (const float*)d_in[4];
    const float* wgate = (const float*)d_in[5];
    const float* wup   = (const float*)d_in[6];
    const float* wdown = (const float*)d_in[7];
    const float* n1w   = (const float*)d_in[8];
    const float* n2w   = (const float*)d_in[9];
    float* out = (float*)d_out;

    __half *h, *qkv, *att, *h2, *act, *cwqkv, *cwo, *cwgu, *cwd;
    float *x2;
    cudaGetSymbolAddress((void**)&h,     g_h);
    cudaGetSymbolAddress((void**)&qkv,   g_qkv);
    cudaGetSymbolAddress((void**)&att,   g_att);
    cudaGetSymbolAddress((void**)&x2,    g_x2);
    cudaGetSymbolAddress((void**)&h2,    g_h2);
    cudaGetSymbolAddress((void**)&act,   g_act);
    cudaGetSymbolAddress((void**)&cwqkv, g_wqkv);
    cudaGetSymbolAddress((void**)&cwo,   g_wo);
    cudaGetSymbolAddress((void**)&cwgu,  g_wgu);
    cudaGetSymbolAddress((void**)&cwd,   g_wd);

    cudaFuncSetAttribute(gemm_fp16<__half>, cudaFuncAttributeMaxDynamicSharedMemorySize, GEMM_DSM);
    cudaFuncSetAttribute(gemm_fp16<float>,  cudaFuncAttributeMaxDynamicSharedMemorySize, GEMM_DSM);
    cudaFuncSetAttribute(gemm_gu,           cudaFuncAttributeMaxDynamicSharedMemorySize, GEMM_DSM);

    // weight conversion
    int nw1 = DIM * DIM / 4, nw2 = HIDDEN * DIM / 4;
    cvt_qkv_kernel<<<(3 * nw1 + 255) / 256, 256>>>(wq, wk, wv, cwqkv, nw1);
    cvt_gu_kernel<<<(2 * nw2 + 255) / 256, 256>>>(wgate, wup, cwgu, nw2);
    cvt_fp16_kernel<<<(nw1 + 255) / 256, 256>>>(wo, cwo, nw1);
    cvt_fp16_kernel<<<(nw2 + 255) / 256, 256>>>(wdown, cwd, nw2);

    rmsnorm_kernel<<<NTOK, 256>>>(x, n1w, h);

    dim3 gq(3 * DIM / 128, NTOK / 128);
    gemm_fp16<__half><<<gq, 256, GEMM_DSM>>>(h, cwqkv, nullptr, qkv, DIM, 3 * DIM);

    dim3 ga(SEQ / 64, NHEADS, BATCH);
    attn_fp16<<<ga, 128>>>(qkv, att);

    dim3 g1(DIM / 128, NTOK / 128);
    gemm_fp16<float><<<g1, 256, GEMM_DSM>>>(att, cwo, x, x2, DIM, DIM);

    rmsnorm_kernel<<<NTOK, 256>>>(x2, n2w, h2);

    dim3 g2(2 * HIDDEN / 128, NTOK / 128);
    gemm_gu<<<g2, 256, GEMM_DSM>>>(h2, cwgu, act, DIM);

    gemm_fp16<float><<<g1, 256, GEMM_DSM>>>(act, cwd, x2, out, HIDDEN, DIM);
}

// round 8
// speedup vs baseline: 6.6597x; 1.0290x over previous
#include <cuda_runtime.h>
#include <cuda_fp16.h>
#include <math.h>
#include <math_constants.h>
#include <stdint.h>

#define DIM     1024
#define NHEADS  16
#define HDIM    64
#define HIDDEN  4096
#define BATCH   2
#define SEQ     2048
#define NTOK    (BATCH * SEQ)
#define EPS     1e-5f

// ---------------- scratch (static device globals; no allocs) ----------------
__device__ __half g_h   [NTOK * DIM];         // rmsnorm1 out
__device__ __half g_qkv [NTOK * 3 * DIM];     // fused qkv out (fp16)
__device__ __half g_att [NTOK * DIM];         // attention out
__device__ float  g_x2  [NTOK * DIM];         // residual after attention
__device__ __half g_h2  [NTOK * DIM];         // rmsnorm2 out
__device__ __half g_act [NTOK * HIDDEN];      // silu(gate)*up (fp16)
// fp16 weights: wqkv = [wq;wk;wv] rows; wgu rows interleaved gate/up
__device__ __half g_wqkv[3 * DIM * DIM];
__device__ __half g_wo  [DIM * DIM];
__device__ __half g_wgu [2 * HIDDEN * DIM];
__device__ __half g_wd  [DIM * HIDDEN];

// ---------------- helpers ----------------
__device__ __forceinline__ void cp16(unsigned dst, const void* src) {
    asm volatile("cp.async.cg.shared.global [%0], [%1], 16;\n" :: "r"(dst), "l"(src));
}
__device__ __forceinline__ void cp_commit() {
    asm volatile("cp.async.commit_group;\n");
}
template <int N>
__device__ __forceinline__ void cp_wait() {
    asm volatile("cp.async.wait_group %0;\n" :: "n"(N));
}
__device__ __forceinline__ unsigned smem_u32(const void* p) {
    return (unsigned)__cvta_generic_to_shared(p);
}
__device__ __forceinline__ float ex2f(float x) {
    float r; asm("ex2.approx.f32 %0, %1;" : "=f"(r) : "f"(x)); return r;
}
__device__ __forceinline__ float silu_fast(float x) {
    // x / (1 + 2^(-x*log2e))
    return x / (1.0f + ex2f(-1.44269504089f * x));
}
__device__ __forceinline__ uint32_t packh2(float a, float b) {
    __half2 h = __floats2half2_rn(a, b);
    return *reinterpret_cast<uint32_t*>(&h);
}
#define LDMX4(r0, r1, r2, r3, addr) \
    asm volatile("ldmatrix.sync.aligned.m8n8.x4.shared.b16 {%0,%1,%2,%3}, [%4];" \
                 : "=r"(r0), "=r"(r1), "=r"(r2), "=r"(r3) : "r"(addr))
#define LDMX4T(r0, r1, r2, r3, addr) \
    asm volatile("ldmatrix.sync.aligned.m8n8.x4.trans.shared.b16 {%0,%1,%2,%3}, [%4];" \
                 : "=r"(r0), "=r"(r1), "=r"(r2), "=r"(r3) : "r"(addr))
#define MMA16816(c, a0, a1, a2, a3, b0, b1) \
    asm volatile("mma.sync.aligned.m16n8k16.row.col.f32.f16.f16.f32 " \
                 "{%0,%1,%2,%3}, {%4,%5,%6,%7}, {%8,%9}, {%0,%1,%2,%3};" \
                 : "+f"((c)[0]), "+f"((c)[1]), "+f"((c)[2]), "+f"((c)[3]) \
                 : "r"(a0), "r"(a1), "r"(a2), "r"(a3), "r"(b0), "r"(b1))

// ---------------- fp16 tensor-core GEMM core (NT, 3-stage pipeline) ---------
// A: [M,K] fp16 row-major, B: [N,K] fp16 row-major.
// 128x128 tile, BK=32, 8 warps (2x4), warp tile 64x32, 2 CTAs/SM.
#define LDH        40
#define TILE_BYTES (128 * LDH * 2)          // 10240
#define STG_BYTES  (2 * TILE_BYTES)         // A+B per stage
#define GEMM_DSM   (3 * STG_BYTES)          // 61440 (x2 CTAs = 122880 < 228KB)

__device__ __forceinline__ void fill_stage_h(unsigned stgbase,
                                             const __half* A, const __half* B,
                                             int K, int m0, int n0, int kt, int tid) {
    int row = tid >> 2;
    int kc  = tid & 3;
    const __half* ag = A + (size_t)(m0 + row) * K + kt * 32 + kc * 8;
    const __half* bg = B + (size_t)(n0 + row) * K + kt * 32 + kc * 8;
    unsigned off  = (unsigned)(row * LDH * 2 + kc * 16);
    unsigned off2 = off + 64 * LDH * 2;
    size_t gstep = (size_t)64 * K;
    cp16(stgbase + off,  ag);
    cp16(stgbase + off2, ag + gstep);
    cp16(stgbase + TILE_BYTES + off,  bg);
    cp16(stgbase + TILE_BYTES + off2, bg + gstep);
    cp_commit();
}

__device__ __forceinline__ void gemm_mainloop(float acc[4][4][4],
                                              const __half* A, const __half* B,
                                              int K, int m0, int n0,
                                              int tid, int lane, int wid,
                                              int wm, int wn, unsigned base) {
    #pragma unroll
    for (int i = 0; i < 4; i++)
        #pragma unroll
        for (int j = 0; j < 4; j++)
            #pragma unroll
            for (int c = 0; c < 4; c++) acc[i][j][c] = 0.0f;

    const int NT = K >> 5;
    fill_stage_h(base,             A, B, K, m0, n0, 0, tid);
    fill_stage_h(base + STG_BYTES, A, B, K, m0, n0, 1, tid);

    unsigned lrow = (unsigned)(lane & 15);
    unsigned lcolb = (unsigned)((lane >> 4) * 16);

    int st = 0;
    for (int it = 0; it < NT; it++) {
        cp_wait<1>();
        __syncthreads();

        if (it + 2 < NT) {
            int fs = st + 2; if (fs >= 3) fs -= 3;
            fill_stage_h(base + fs * STG_BYTES, A, B, K, m0, n0, it + 2, tid);
        } else {
            cp_commit();
        }

        unsigned bA = base + st * STG_BYTES;
        unsigned bB = bA + TILE_BYTES;
        #pragma unroll
        for (int ks = 0; ks < 2; ks++) {
            unsigned kbyte = (unsigned)(ks * 32) + lcolb;
            uint32_t af[4][4], bf[2][4];
            #pragma unroll
            for (int mi = 0; mi < 4; mi++) {
                unsigned addr = bA + (unsigned)((wm + mi * 16 + lrow) * LDH * 2) + kbyte;
                LDMX4(af[mi][0], af[mi][1], af[mi][2], af[mi][3], addr);
            }
            #pragma unroll
            for (int nb = 0; nb < 2; nb++) {
                unsigned addr = bB + (unsigned)((wn + nb * 16 + lrow) * LDH * 2) + kbyte;
                LDMX4(bf[nb][0], bf[nb][1], bf[nb][2], bf[nb][3], addr);
            }
            #pragma unroll
            for (int mi = 0; mi < 4; mi++) {
                #pragma unroll
                for (int ni = 0; ni < 4; ni++) {
                    int nb = ni >> 1, blk = ni & 1;
                    MMA16816(acc[mi][ni], af[mi][0], af[mi][1], af[mi][2], af[mi][3],
                             bf[nb][blk], bf[nb][blk + 2]);
                }
            }
        }
        st++; if (st == 3) st = 0;
    }
}

template<typename OT>
__global__ __launch_bounds__(256, 2)
void gemm_fp16(const __half* __restrict__ A, const __half* __restrict__ B,
               const float* __restrict__ res, OT* __restrict__ C,
               int K, int ldc) {
    extern __shared__ __half dyn[];
    unsigned base = smem_u32(dyn);
    int tid = threadIdx.x, lane = tid & 31, wid = tid >> 5;
    int wm = (wid & 1) * 64, wn = (wid >> 1) * 32;
    int m0 = blockIdx.y * 128, n0 = blockIdx.x * 128;

    float acc[4][4][4];
    gemm_mainloop(acc, A, B, K, m0, n0, tid, lane, wid, wm, wn, base);

    int gr = lane >> 2;
    int gc = (lane & 3) * 2;
    #pragma unroll
    for (int mi = 0; mi < 4; mi++) {
        #pragma unroll
        for (int ni = 0; ni < 4; ni++) {
            size_t row = (size_t)(m0 + wm + mi * 16 + gr);
            size_t col = (size_t)(n0 + wn + ni * 8 + gc);
            float v[4] = { acc[mi][ni][0], acc[mi][ni][1], acc[mi][ni][2], acc[mi][ni][3] };
            if (res) {
                float2 r0 = *reinterpret_cast<const float2*>(res + row * ldc + col);
                float2 r1 = *reinterpret_cast<const float2*>(res + (row + 8) * ldc + col);
                v[0] += r0.x; v[1] += r0.y; v[2] += r1.x; v[3] += r1.y;
            }
            if (sizeof(OT) == 4) {
                float* Cf = (float*)C;
                *reinterpret_cast<float2*>(Cf + row * ldc + col) = make_float2(v[0], v[1]);
                *reinterpret_cast<float2*>(Cf + (row + 8) * ldc + col) = make_float2(v[2], v[3]);
            } else {
                __half* Ch = (__half*)C;
                *reinterpret_cast<__half2*>(Ch + row * ldc + col) = __floats2half2_rn(v[0], v[1]);
                *reinterpret_cast<__half2*>(Ch + (row + 8) * ldc + col) = __floats2half2_rn(v[2], v[3]);
            }
        }
    }
}

// gate/up GEMM with fused SiLU epilogue. B rows interleaved (2j=gate_j, 2j+1=up_j).
__global__ __launch_bounds__(256, 2)
void gemm_gu(const __half* __restrict__ A, const __half* __restrict__ B,
             __half* __restrict__ act, int K) {
    extern __shared__ __half dyn[];
    unsigned base = smem_u32(dyn);
    int tid = threadIdx.x, lane = tid & 31, wid = tid >> 5;
    int wm = (wid & 1) * 64, wn = (wid >> 1) * 32;
    int m0 = blockIdx.y * 128, n0 = blockIdx.x * 128;

    float acc[4][4][4];
    gemm_mainloop(acc, A, B, K, m0, n0, tid, lane, wid, wm, wn, base);

    int gr = lane >> 2;
    int gc = (lane & 3) * 2;
    #pragma unroll
    for (int mi = 0; mi < 4; mi++) {
        #pragma unroll
        for (int ni = 0; ni < 4; ni++) {
            size_t row = (size_t)(m0 + wm + mi * 16 + gr);
            int col = n0 + wn + ni * 8 + gc;          // even: gate, odd: up
            float r0 = silu_fast(acc[mi][ni][0]) * acc[mi][ni][1];
            float r1 = silu_fast(acc[mi][ni][2]) * acc[mi][ni][3];
            act[row * HIDDEN + (col >> 1)]       = __float2half_rn(r0);
            act[(row + 8) * HIDDEN + (col >> 1)] = __float2half_rn(r1);
        }
    }
}

// ---------------- fp16 tensor-core causal flash attention -------------------
#define LDHA 72
#define LDQKV (3 * DIM)

__global__ __launch_bounds__(128)
void attn_fp16(const __half* __restrict__ QKV, __half* __restrict__ O) {
    __shared__ __half Qs[64 * LDHA];
    __shared__ __half Ks[2][64 * LDHA];
    __shared__ __half Vs[2][64 * LDHA];

    int qb = blockIdx.x, h = blockIdx.y, b = blockIdx.z;
    int tid = threadIdx.x, lane = tid & 31, wid = tid >> 5;
    const float SC = 0.125f * 1.44269504089f;

    const __half* Qg = QKV + (size_t)b * SEQ * LDQKV + h * HDIM;
    const __half* Kg = Qg + DIM;
    const __half* Vg = Qg + 2 * DIM;

    #pragma unroll
    for (int i = 0; i < 4; i++) {
        int id = tid + i * 128;
        int row = id >> 3, ch = id & 7;
        cp16(smem_u32(Qs) + row * (LDHA * 2) + ch * 16,
             Qg + (size_t)(qb * 64 + row) * LDQKV + ch * 8);
    }
    #pragma unroll
    for (int i = 0; i < 4; i++) {
        int id = tid + i * 128;
        int row = id >> 3, ch = id & 7;
        unsigned so = (unsigned)(row * (LDHA * 2) + ch * 16);
        size_t go = (size_t)row * LDQKV + ch * 8;
        cp16(smem_u32(Ks[0]) + so, Kg + go);
        cp16(smem_u32(Vs[0]) + so, Vg + go);
    }
    cp_commit();

    float o[8][4];
    #pragma unroll
    for (int j = 0; j < 8; j++)
        #pragma unroll
        for (int e = 0; e < 4; e++) o[j][e] = 0.0f;
    float m0 = -CUDART_INF_F, m1 = -CUDART_INF_F, l0 = 0.0f, l1 = 0.0f;

    unsigned lrow = (unsigned)(lane & 15);
    unsigned lcolb = (unsigned)((lane >> 4) * 16);
    unsigned qaddr = smem_u32(Qs) + (wid * 16 + lrow) * (LDHA * 2) + lcolb;

    for (int kb = 0; kb <= qb; kb++) {
        if (kb) __syncthreads();

        if (kb < qb) {
            int s = (kb + 1) & 1;
            #pragma unroll
            for (int i = 0; i < 4; i++) {
                int id = tid + i * 128;
                int row = id >> 3, ch = id & 7;
                unsigned so = (unsigned)(row * (LDHA * 2) + ch * 16);
                size_t go = (size_t)((kb + 1) * 64 + row) * LDQKV + ch * 8;
                cp16(smem_u32(Ks[s]) + so, Kg + go);
                cp16(smem_u32(Vs[s]) + so, Vg + go);
            }
        }
        cp_commit();
        cp_wait<1>();
        __syncthreads();

        int st = kb & 1;
        unsigned kbase = smem_u32(Ks[st]) + lrow * (LDHA * 2) + lcolb;
        unsigned vbase = smem_u32(Vs[st]) + lrow * (LDHA * 2) + lcolb;

        float s[8][4];
        #pragma unroll
        for (int j = 0; j < 8; j++)
            #pragma unroll
            for (int e = 0; e < 4; e++) s[j][e] = 0.0f;
        #pragma unroll
        for (int kk = 0; kk < 4; kk++) {
            uint32_t aq0, aq1, aq2, aq3;
            LDMX4(aq0, aq1, aq2, aq3, qaddr + kk * 32);
            #pragma unroll
            for (int nb = 0; nb < 4; nb++) {
                uint32_t b0, b1, b2, b3;
                LDMX4(b0, b1, b2, b3, kbase + (unsigned)(nb * 16 * LDHA * 2) + kk * 32);
                MMA16816(s[nb * 2],     aq0, aq1, aq2, aq3, b0, b2);
                MMA16816(s[nb * 2 + 1], aq0, aq1, aq2, aq3, b1, b3);
            }
        }

        int r0 = wid * 16 + (lane >> 2);
        int c0 = (lane & 3) * 2;
        if (kb == qb) {
            #pragma unroll
            for (int j = 0; j < 8; j++) {
                int col = j * 8 + c0;
                #pragma unroll
                for (int e = 0; e < 4; e++) {
                    int row = r0 + (e >> 1) * 8;
                    int cc  = col + (e & 1);
                    s[j][e] = (cc > row) ? -CUDART_INF_F : s[j][e] * SC;
                }
            }
        } else {
            #pragma unroll
            for (int j = 0; j < 8; j++)
                #pragma unroll
                for (int e = 0; e < 4; e++) s[j][e] *= SC;
        }

        float rm0 = -CUDART_INF_F, rm1 = -CUDART_INF_F;
        #pragma unroll
        for (int j = 0; j < 8; j++) {
            rm0 = fmaxf(rm0, fmaxf(s[j][0], s[j][1]));
            rm1 = fmaxf(rm1, fmaxf(s[j][2], s[j][3]));
        }
        rm0 = fmaxf(rm0, __shfl_xor_sync(0xFFFFFFFFu, rm0, 1));
        rm0 = fmaxf(rm0, __shfl_xor_sync(0xFFFFFFFFu, rm0, 2));
        rm1 = fmaxf(rm1, __shfl_xor_sync(0xFFFFFFFFu, rm1, 1));
        rm1 = fmaxf(rm1, __shfl_xor_sync(0xFFFFFFFFu, rm1, 2));
        float mn0 = fmaxf(m0, rm0), mn1 = fmaxf(m1, rm1);
        float a0 = ex2f(m0 - mn0), a1 = ex2f(m1 - mn1);
        m0 = mn0; m1 = mn1;
        float rs0 = 0.0f, rs1 = 0.0f;
        #pragma unroll
        for (int j = 0; j < 8; j++) {
            s[j][0] = ex2f(s[j][0] - mn0); rs0 += s[j][0];
            s[j][1] = ex2f(s[j][1] - mn0); rs0 += s[j][1];
            s[j][2] = ex2f(s[j][2] - mn1); rs1 += s[j][2];
            s[j][3] = ex2f(s[j][3] - mn1); rs1 += s[j][3];
        }
        rs0 += __shfl_xor_sync(0xFFFFFFFFu, rs0, 1);
        rs0 += __shfl_xor_sync(0xFFFFFFFFu, rs0, 2);
        rs1 += __shfl_xor_sync(0xFFFFFFFFu, rs1, 1);
        rs1 += __shfl_xor_sync(0xFFFFFFFFu, rs1, 2);
        l0 = l0 * a0 + rs0;
        l1 = l1 * a1 + rs1;

        #pragma unroll
        for (int j = 0; j < 8; j++) {
            o[j][0] *= a0; o[j][1] *= a0; o[j][2] *= a1; o[j][3] *= a1;
        }
        #pragma unroll
        for (int kk = 0; kk < 4; kk++) {
            uint32_t p0 = packh2(s[2 * kk][0],     s[2 * kk][1]);
            uint32_t p1 = packh2(s[2 * kk][2],     s[2 * kk][3]);
            uint32_t p2 = packh2(s[2 * kk + 1][0], s[2 * kk + 1][1]);
            uint32_t p3 = packh2(s[2 * kk + 1][2], s[2 * kk + 1][3]);
            #pragma unroll
            for (int nb2 = 0; nb2 < 4; nb2++) {
                uint32_t v0, v1, v2, v3;
                LDMX4T(v0, v1, v2, v3,
                       vbase + (unsigned)(kk * 16 * LDHA * 2) + nb2 * 32);
                MMA16816(o[nb2 * 2],     p0, p1, p2, p3, v0, v1);
                MMA16816(o[nb2 * 2 + 1], p0, p1, p2, p3, v2, v3);
            }
        }
    }

    float inv0 = 1.0f / l0, inv1 = 1.0f / l1;
    int row_g = qb * 64 + wid * 16 + (lane >> 2);
    size_t ob = (size_t)(b * SEQ + row_g) * DIM + h * HDIM + (lane & 3) * 2;
    #pragma unroll
    for (int j = 0; j < 8; j++) {
        *reinterpret_cast<__half2*>(O + ob + j * 8) =
            __floats2half2_rn(o[j][0] * inv0, o[j][1] * inv0);
        *reinterpret_cast<__half2*>(O + ob + 8 * DIM + j * 8) =
            __floats2half2_rn(o[j][2] * inv1, o[j][3] * inv1);
    }
}

// ---------------- single fused weight-conversion kernel ---------------------
// regions (in float4 units): qkv: 3*nw1 (wq,wk,wv concat); gu: 2*nw2 interleaved;
// wo: nw1; wd: nw2.  nw1 = DIM*DIM/4, nw2 = HIDDEN*DIM/4.
__global__ void cvt_all_kernel(const float* __restrict__ wq, const float* __restrict__ wk,
                               const float* __restrict__ wv, const float* __restrict__ wo,
                               const float* __restrict__ wgate, const float* __restrict__ wup,
                               const float* __restrict__ wdown,
                               __half* __restrict__ dqkv, __half* __restrict__ dgu,
                               __half* __restrict__ dwo, __half* __restrict__ dwd) {
    const int nw1 = DIM * DIM / 4, nw2 = HIDDEN * DIM / 4;
    int i = blockIdx.x * blockDim.x + threadIdx.x;
    const float* src;
    __half* dst;
    int di;
    if (i < 3 * nw1) {                         // qkv concat
        src = (i < nw1) ? (wq + (size_t)i * 4)
            : (i < 2 * nw1) ? (wk + (size_t)(i - nw1) * 4)
            : (wv + (size_t)(i - 2 * nw1) * 4);
        dst = dqkv; di = i;
    } else if (i < 3 * nw1 + 2 * nw2) {        // gu interleaved
        int j = i - 3 * nw1;
        int r = j >> 8, c = j & 255;           // DIM/4=256 f4 per row
        src = ((r & 1) ? wup : wgate) + (size_t)(r >> 1) * DIM + c * 4;
        dst = dgu; di = j;
    } else if (i < 4 * nw1 + 2 * nw2) {        // wo
        int j = i - 3 * nw1 - 2 * nw2;
        src = wo + (size_t)j * 4;
        dst = dwo; di = j;
    } else if (i < 4 * nw1 + 3 * nw2) {        // wd
        int j = i - 4 * nw1 - 2 * nw2;
        src = wdown + (size_t)j * 4;
        dst = dwd; di = j;
    } else return;
    float4 v = *reinterpret_cast<const float4*>(src);
    reinterpret_cast<__half2*>(dst)[di * 2]     = __floats2half2_rn(v.x, v.y);
    reinterpret_cast<__half2*>(dst)[di * 2 + 1] = __floats2half2_rn(v.z, v.w);
}

// ---------------- RMSNorm: one block per token, fp16 out ----------------
__global__ void rmsnorm_kernel(const float* __restrict__ x,
                               const float* __restrict__ w,
                               __half* __restrict__ out) {
    int t = blockIdx.x;
    int tid = threadIdx.x;
    const float4* xr = reinterpret_cast<const float4*>(x + (size_t)t * DIM);
    float4 v = xr[tid];
    float ss = v.x * v.x + v.y * v.y + v.z * v.z + v.w * v.w;
    #pragma unroll
    for (int o = 16; o > 0; o >>= 1) ss += __shfl_xor_sync(0xFFFFFFFFu, ss, o);
    __shared__ float red[8];
    if ((tid & 31) == 0) red[tid >> 5] = ss;
    __syncthreads();
    if (tid < 8) {
        float s = red[tid];
        #pragma unroll
        for (int o = 4; o > 0; o >>= 1) s += __shfl_xor_sync(0xFFu, s, o);
        if (tid == 0) red[0] = s;
    }
    __syncthreads();
    float scale = rsqrtf(red[0] * (1.0f / DIM) + EPS);
    float4 wv = reinterpret_cast<const float4*>(w)[tid];
    __half2* op = reinterpret_cast<__half2*>(out + (size_t)t * DIM) + tid * 2;
    op[0] = __floats2half2_rn(v.x * scale * wv.x, v.y * scale * wv.y);
    op[1] = __floats2half2_rn(v.z * scale * wv.z, v.w * scale * wv.w);
}

// ---------------- launch ----------------
extern "C" void kernel_launch(void* const* d_in, const int* in_sizes, int n_in,
                              void* d_out, int out_size) {
    const float* x     = (const float*)d_in[0];
    const float* wq    = (const float*)d_in[1];
    const float* wk    = (const float*)d_in[2];
    const float* wv    = (const float*)d_in[3];
    const float* wo    = (const float*)d_in[4];
    const float* wgate = (const float*)d_in[5];
    const float* wup   = (const float*)d_in[6];
    const float* wdown = (const float*)d_in[7];
    const float* n1w   = (const float*)d_in[8];
    const float* n2w   = (const float*)d_in[9];
    float* out = (float*)d_out;

    __half *h, *qkv, *att, *h2, *act, *cwqkv, *cwo, *cwgu, *cwd;
    float *x2;
    cudaGetSymbolAddress((void**)&h,     g_h);
    cudaGetSymbolAddress((void**)&qkv,   g_qkv);
    cudaGetSymbolAddress((void**)&att,   g_att);
    cudaGetSymbolAddress((void**)&x2,    g_x2);
    cudaGetSymbolAddress((void**)&h2,    g_h2);
    cudaGetSymbolAddress((void**)&act,   g_act);
    cudaGetSymbolAddress((void**)&cwqkv, g_wqkv);
    cudaGetSymbolAddress((void**)&cwo,   g_wo);
    cudaGetSymbolAddress((void**)&cwgu,  g_wgu);
    cudaGetSymbolAddress((void**)&cwd,   g_wd);

    cudaFuncSetAttribute(gemm_fp16<__half>, cudaFuncAttributeMaxDynamicSharedMemorySize, GEMM_DSM);
    cudaFuncSetAttribute(gemm_fp16<float>,  cudaFuncAttributeMaxDynamicSharedMemorySize, GEMM_DSM);
    cudaFuncSetAttribute(gemm_gu,           cudaFuncAttributeMaxDynamicSharedMemorySize, GEMM_DSM);

    // fused weight conversion (all 7 weights, 1 launch)
    int nw1 = DIM * DIM / 4, nw2 = HIDDEN * DIM / 4;
    int ncvt = 4 * nw1 + 3 * nw2;
    cvt_all_kernel<<<(ncvt + 255) / 256, 256>>>(wq, wk, wv, wo, wgate, wup, wdown,
                                                cwqkv, cwgu, cwo, cwd);

    rmsnorm_kernel<<<NTOK, 256>>>(x, n1w, h);

    dim3 gq(3 * DIM / 128, NTOK / 128);
    gemm_fp16<__half><<<gq, 256, GEMM_DSM>>>(h, cwqkv, nullptr, qkv, DIM, 3 * DIM);

    dim3 ga(SEQ / 64, NHEADS, BATCH);
    attn_fp16<<<ga, 128>>>(qkv, att);

    dim3 g1(DIM / 128, NTOK / 128);
    gemm_fp16<float><<<g1, 256, GEMM_DSM>>>(att, cwo, x, x2, DIM, DIM);

    rmsnorm_kernel<<<NTOK, 256>>>(x2, n2w, h2);

    dim3 g2(2 * HIDDEN / 128, NTOK / 128);
    gemm_gu<<<g2, 256, GEMM_DSM>>>(h2, cwgu, act, DIM);

    gemm_fp16<float><<<g1, 256, GEMM_DSM>>>(act, cwd, x2, out, HIDDEN, DIM);
}